// round 14
// baseline (speedup 1.0000x reference)
#include <cuda_runtime.h>
#include <cuda_bf16.h>
#include <cstdint>
#include <cstddef>

#define BATCH 4
#define NPTS  4096
#define PTOT  (BATCH*NPTS)     /* 16384 */
#define KNN   16
#define EDGES (PTOT*KNN)       /* 262144 */
#define FLTMAX 3.402823466e+38f

// ---------------- scratch ----------------
__device__ int      d_idx[EDGES];
__device__ float    d_Ap[PTOT*64];
__device__ float    d_Cp[PTOT*64];
__device__ unsigned d_xenc[PTOT*256];
__device__ __align__(16) __nv_bfloat16 d_g1hi[PTOT*256], d_g1lo[PTOT*256];
__device__ __align__(16) __nv_bfloat16 d_g2hi[PTOT*512], d_g2lo[PTOT*512];
__device__ unsigned d_scene[BATCH*1024];
__device__ float    d_ph1[BATCH*512];
__device__ float    d_cb[2176];

// split weights (gamma-folded): [N, KPAD] bf16, hi/lo
__device__ __align__(16) __nv_bfloat16 d_w1hi[128*64],   d_w1lo[128*64];
__device__ __align__(16) __nv_bfloat16 d_w2hi[256*128],  d_w2lo[256*128];
__device__ __align__(16) __nv_bfloat16 d_w3hi[256*320],  d_w3lo[256*320];
__device__ __align__(16) __nv_bfloat16 d_w4hi[512*256],  d_w4lo[512*256];
__device__ __align__(16) __nv_bfloat16 d_w5hi[1024*512], d_w5lo[1024*512];

__device__ __forceinline__ unsigned encf(float f){
    unsigned u = __float_as_uint(f);
    return (u & 0x80000000u) ? ~u : (u | 0x80000000u);
}
__device__ __forceinline__ float decf(unsigned u){
    return __uint_as_float((u & 0x80000000u) ? (u ^ 0x80000000u) : ~u);
}
__device__ __forceinline__ uint32_t smem_u32(const void* p){
    uint32_t a;
    asm("{ .reg .u64 t; cvta.to.shared.u64 t, %1; cvt.u32.u64 %0, t; }" : "=r"(a) : "l"(p));
    return a;
}
__device__ __forceinline__ void cp_async16(void* smem, const void* gmem){
    unsigned s = (unsigned)__cvta_generic_to_shared(smem);
    asm volatile("cp.async.cg.shared.global [%0], [%1], 16;\n" :: "r"(s), "l"(gmem));
}
__device__ __forceinline__ void cp_commit(){ asm volatile("cp.async.commit_group;\n"); }
template<int N> __device__ __forceinline__ void cp_wait(){
    asm volatile("cp.async.wait_group %0;\n" :: "n"(N));
}

__device__ __forceinline__ void ldm_x4(uint32_t& r0, uint32_t& r1, uint32_t& r2, uint32_t& r3, uint32_t addr){
    asm volatile("ldmatrix.sync.aligned.m8n8.x4.shared.b16 {%0,%1,%2,%3}, [%4];"
        : "=r"(r0), "=r"(r1), "=r"(r2), "=r"(r3) : "r"(addr));
}
__device__ __forceinline__ void mma_bf16(float* c, const uint32_t* a, const uint32_t* b){
    asm volatile(
        "mma.sync.aligned.m16n8k16.row.col.f32.bf16.bf16.f32 "
        "{%0,%1,%2,%3}, {%4,%5,%6,%7}, {%8,%9}, {%0,%1,%2,%3};"
        : "+f"(c[0]), "+f"(c[1]), "+f"(c[2]), "+f"(c[3])
        : "r"(a[0]), "r"(a[1]), "r"(a[2]), "r"(a[3]), "r"(b[0]), "r"(b[1]));
}
__device__ __forceinline__ uint32_t pk2(__nv_bfloat16 a, __nv_bfloat16 b){
    return (uint32_t)__bfloat16_as_ushort(a) | ((uint32_t)__bfloat16_as_ushort(b) << 16);
}
__device__ __forceinline__ void split_pair(uint32_t* hiP, uint32_t* loP, size_t idx2, float v0, float v1){
    __nv_bfloat16 h0 = __float2bfloat16(v0), h1 = __float2bfloat16(v1);
    hiP[idx2] = pk2(h0, h1);
    loP[idx2] = pk2(__float2bfloat16(v0 - __bfloat162float(h0)),
                    __float2bfloat16(v1 - __bfloat162float(h1)));
}

// ---------------- init ----------------
__global__ void init_kernel(){
    int i = blockIdx.x * 256 + threadIdx.x;
    uint4 v = make_uint4(0x00800000u, 0x00800000u, 0x00800000u, 0x00800000u);
    if (i < PTOT*256/4) ((uint4*)d_xenc)[i] = v;
    if (i < BATCH*1024/4) ((uint4*)d_scene)[i] = v;
}

// ---------------- merged prep: Ap/Cp + all weights + fused biases ----------------
#define PREP_AC_N  (PTOT*64)
#define OFF_W      PREP_AC_N
#define PREP_TOTAL (OFF_W + 778240 + 2176)
__global__ void prep_all(
    const float* __restrict__ pos,
    const float* __restrict__ cw1, const float* __restrict__ cb1, const float* __restrict__ cg1, const float* __restrict__ cs1,
    const float* __restrict__ cw2, const float* __restrict__ cg2, const float* __restrict__ cb2, const float* __restrict__ cs2,
    const float* __restrict__ cw3, const float* __restrict__ cb3,
    const float* __restrict__ sw1, const float* __restrict__ sg1, const float* __restrict__ sb1, const float* __restrict__ ss1,
    const float* __restrict__ sw2, const float* __restrict__ sg2, const float* __restrict__ sb2, const float* __restrict__ ss2,
    const float* __restrict__ sw3, const float* __restrict__ sb3)
{
    int raw = blockIdx.x * 256 + threadIdx.x;
    if (raw < PREP_AC_N){
        int p = raw >> 6, j = raw & 63;
        float x = pos[p*3], y = pos[p*3+1], z = pos[p*3+2];
        float w0 = cw1[0*64+j] + cw1[3*64+j];
        float w1 = cw1[1*64+j] + cw1[4*64+j];
        float w2 = cw1[2*64+j] + cw1[5*64+j];
        float a = fmaf(x, w0, fmaf(y, w1, fmaf(z, w2, cb1[j])));
        float c = fmaf(x, cw1[3*64+j], fmaf(y, cw1[4*64+j], z*cw1[5*64+j]));
        float g = cg1[j];
        d_Ap[raw] = fmaf(a, g, cs1[j]);
        d_Cp[raw] = c * g;
        return;
    }
    int idx = raw - OFF_W;
    const float* W; const float* G = nullptr;
    __nv_bfloat16 *hi, *lo;
    int Kt, Nt, KPAD, base;
    if (idx < 8192){        W=cw2; G=cg2; hi=d_w1hi; lo=d_w1lo; Kt=64;  Nt=128;  KPAD=64;  base=0; }
    else if (idx < 40960){  W=cw3;        hi=d_w2hi; lo=d_w2lo; Kt=128; Nt=256;  KPAD=128; base=8192; }
    else if (idx < 122880){ W=sw1; G=sg1; hi=d_w3hi; lo=d_w3lo; Kt=259; Nt=256;  KPAD=320; base=40960; }
    else if (idx < 253952){ W=sw2; G=sg2; hi=d_w4hi; lo=d_w4lo; Kt=256; Nt=512;  KPAD=256; base=122880; }
    else if (idx < 778240){ W=sw3;        hi=d_w5hi; lo=d_w5lo; Kt=512; Nt=1024; KPAD=512; base=253952; }
    else if (idx < 780416){
        int j = idx - 778240;
        if (j < 128)            d_cb[j] = fmaf(cb2[j], cg2[j], cs2[j]);
        else if (j < 384)       d_cb[j] = cb3[j-128];
        else if (j < 640)       d_cb[j] = fmaf(sb1[j-384], sg1[j-384], ss1[j-384]);
        else if (j < 1152)      d_cb[j] = fmaf(sb2[j-640], sg2[j-640], ss2[j-640]);
        else                    d_cb[j] = sb3[j-1152];
        return;
    } else return;
    int li = idx - base;
    int n = li / KPAD, k = li % KPAD;
    float g = G ? G[n] : 1.f;
    float v = (k < Kt) ? W[(size_t)k * Nt + n] * g : 0.f;
    __nv_bfloat16 h = __float2bfloat16(v);
    hi[li] = h;
    lo[li] = __float2bfloat16(v - __bfloat162float(h));
}

// ---------------- kNN (R9-proven) ----------------
#define KBUF 96
#define KNN_SMEM (3*NPTS*4 + 8*2*KBUF*4)

__global__ __launch_bounds__(256) void knn_kernel(const float* __restrict__ pos){
    extern __shared__ float kb[];
    float* sx = kb; float* sy = kb + NPTS; float* sz = kb + 2*NPTS;
    int b  = blockIdx.x >> 9;
    int s0 = (blockIdx.x & 511) * 8;
    const float* pb = pos + (size_t)b * NPTS * 3;
    for (int i = threadIdx.x; i < NPTS; i += 256){
        sx[i] = pb[3*i]; sy[i] = pb[3*i+1]; sz[i] = pb[3*i+2];
    }
    __syncthreads();

    const int w = threadIdx.x >> 5, lane = threadIdx.x & 31;
    float* sD = kb + 3*NPTS + w * 2 * KBUF;
    int*   sI = (int*)(sD + KBUF);
    const int src = s0 + w;
    const float qx = sx[src], qy = sy[src], qz = sz[src];
    const unsigned lmask = (1u << lane) - 1u;

    float td = FLTMAX; int ti = 0x7FFFFFFF;
    int cnt = 0;

    auto compact = [&](){
        float cd[3]; unsigned ca[3];
#pragma unroll
        for (int j = 0; j < 3; j++){
            int e = lane + 32*j;
            bool valid = e < cnt;
            cd[j] = valid ? sD[e] : FLTMAX;
            ca[j] = valid ? ((((unsigned)sI[e]) << 8) | (unsigned)e) : 0xFFFFFFFFu;
        }
        unsigned used = 0;
        float lastd = 0.f; unsigned lasta = 0;
#pragma unroll 1
        for (int r = 0; r < 16; r++){
            float bd = FLTMAX; unsigned ba = 0xFFFFFFFFu;
#pragma unroll
            for (int j = 0; j < 3; j++){
                bool ok = !((used >> j) & 1);
                if (ok && (cd[j] < bd || (cd[j] == bd && ca[j] < ba))){ bd = cd[j]; ba = ca[j]; }
            }
#pragma unroll
            for (int off = 16; off; off >>= 1){
                float od = __shfl_xor_sync(0xffffffffu, bd, off);
                unsigned oa = __shfl_xor_sync(0xffffffffu, ba, off);
                if (od < bd || (od == bd && oa < ba)){ bd = od; ba = oa; }
            }
            unsigned e = ba & 0xFFu;
            if (lane == (int)(e & 31u)) used |= 1u << (e >> 5);
            if (lane == 0){ sD[r] = bd; sI[r] = (int)(ba >> 8); }
            lastd = bd; lasta = ba;
        }
        cnt = 16;
        td = lastd; ti = (int)(lasta >> 8);
        __syncwarp();
    };

    for (int c = lane; c < NPTS; c += 32){
        float dx = qx - sx[c], dy = qy - sy[c], dz = qz - sz[c];
        float d = __fadd_rn(__fadd_rn(__fmul_rn(dx,dx), __fmul_rn(dy,dy)), __fmul_rn(dz,dz));
        bool surv = (d < td) || (d == td && c < ti);
        unsigned m = __ballot_sync(0xffffffffu, surv);
        if (m){
            int pos2 = cnt + __popc(m & lmask);
            if (surv){ sD[pos2] = d; sI[pos2] = c; }
            cnt += __popc(m);
            if (cnt > KBUF - 32) compact();
        }
    }
    compact();

    if (lane < KNN)
        d_idx[(b*NPTS + src) * KNN + lane] = b*NPTS + sI[lane];
}

// ================= fused edge pipeline — 512 threads, 16 warps =================
#define EF_SMEM 225280

__global__ __launch_bounds__(512, 1)
void edge_fused(const __nv_bfloat16* __restrict__ w1h, const __nv_bfloat16* __restrict__ w1l,
                const __nv_bfloat16* __restrict__ w2h, const __nv_bfloat16* __restrict__ w2l,
                const float* __restrict__ cbA, const float* __restrict__ cbB)
{
    extern __shared__ char dsm[];
    const uint32_t sb = smem_u32(dsm);

    const int tid  = threadIdx.x;
    const int lane = tid & 31;
    const int warp = tid >> 5;          // 0..15
    const int wr = warp >> 2;           // 0..3 (32-row slab)
    const int wc = warp & 3;            // 0..3
    const int m0 = blockIdx.x * 128;

    auto W1T = [&](int ch, int pl){ return (uint32_t)((ch*2 + pl) * 10240); };
    auto AG  = [&](int pl){ return (uint32_t)(40960 + pl*10240); };
    auto H2T = [&](int ch, int pl){ return (uint32_t)(61440 + ch*20480 + pl*10240); };
    auto W2T = [&](int buf, int pl){ return (uint32_t)(143360 + buf*40960 + pl*20480); };

    // loader: 512 threads, row lr = tid>>2, 8 cols at (tid&3)*8
    const int lr  = tid >> 2;
    const int lc0 = (tid & 3) * 8;
    const int am  = m0 + lr;
    const int tgt1 = d_idx[am];

    // W1: 2048 16B units over 512 threads (4 iters)
#pragma unroll
    for (int i = 0; i < 4; i++){
        int idx = tid + i*512;
        int unit = idx & 511, grp = idx >> 9;
        int row = unit >> 2, c = unit & 3;
        int ch = grp & 1, pl = grp >> 1;
        const __nv_bfloat16* src = (pl ? w1l : w1h) + (size_t)row*64 + ch*32 + c*8;
        cp_async16(dsm + W1T(ch, pl) + row*80 + c*16, src);
    }
    cp_commit();

    auto cpW2 = [&](int ch, int buf){
#pragma unroll
        for (int i = 0; i < 4; i++){
            int idx = tid + i*512;
            int pl = idx >> 10;
            int unit = idx & 1023;
            int row = unit >> 2, c = unit & 3;
            const __nv_bfloat16* src = (pl ? w2l : w2h) + (size_t)row*128 + ch*32 + c*8;
            cp_async16(dsm + W2T(buf, pl) + row*80 + c*16, src);
        }
    };
    cpW2(0, 0); cp_commit();
    cpW2(1, 1); cp_commit();

    float v[8];
    auto fetchA = [&](int ch){
        const int k = ch*32 + lc0;
        const float* p1 = d_Ap + (size_t)(am >> 4) * 64 + k;
        const float* p2 = d_Cp + (size_t)tgt1 * 64 + k;
        float4 a0 = *(const float4*)p1, a1 = *(const float4*)(p1+4);
        float4 c0 = *(const float4*)p2, c1 = *(const float4*)(p2+4);
        v[0]=fmaxf(a0.x-c0.x,0.f); v[1]=fmaxf(a0.y-c0.y,0.f);
        v[2]=fmaxf(a0.z-c0.z,0.f); v[3]=fmaxf(a0.w-c0.w,0.f);
        v[4]=fmaxf(a1.x-c1.x,0.f); v[5]=fmaxf(a1.y-c1.y,0.f);
        v[6]=fmaxf(a1.z-c1.z,0.f); v[7]=fmaxf(a1.w-c1.w,0.f);
    };
    auto stsA = [&](){
        __nv_bfloat16 h[8], l[8];
#pragma unroll
        for (int j = 0; j < 8; j++){
            h[j] = __float2bfloat16(v[j]);
            l[j] = __float2bfloat16(v[j] - __bfloat162float(h[j]));
        }
        const uint32_t off = (uint32_t)lr*80 + (uint32_t)lc0*2;
        *(uint4*)(dsm + AG(0) + off) = make_uint4(pk2(h[0],h[1]), pk2(h[2],h[3]), pk2(h[4],h[5]), pk2(h[6],h[7]));
        *(uint4*)(dsm + AG(1) + off) = make_uint4(pk2(l[0],l[1]), pk2(l[2],l[3]), pk2(l[4],l[5]), pk2(l[6],l[7]));
    };

    const int arow = wr*32 + (lane & 15);
    const uint32_t acolL = (uint32_t)((lane >> 4) << 3) * 2;
    const uint32_t bcolL = (uint32_t)(((lane >> 3) & 1) << 3) * 2;

    // ---- Phase A: warp tile 32x32, acc[2][4][4] ----
    float acc[2][4][4];
#pragma unroll
    for (int mt = 0; mt < 2; mt++)
#pragma unroll
        for (int nt = 0; nt < 4; nt++)
#pragma unroll
            for (int e = 0; e < 4; e++) acc[mt][nt][e] = 0.f;

    fetchA(0);
    stsA();
    fetchA(1);
    cp_wait<2>();
    __syncthreads();

    const int browA = wc*32 + (lane & 7) + (((lane >> 4) & 1) << 3);
#pragma unroll
    for (int ch = 0; ch < 2; ch++){
        if (ch == 1){
            __syncthreads();
            stsA();
            __syncthreads();
        }
#pragma unroll
        for (int ks = 0; ks < 2; ks++){
            const int k0 = ks * 16;
            const uint32_t acol = (uint32_t)k0*2 + acolL;
            const uint32_t bcol = (uint32_t)k0*2 + bcolL;
            uint32_t ah[2][4], al[2][4];
#pragma unroll
            for (int mt = 0; mt < 2; mt++){
                ldm_x4(ah[mt][0], ah[mt][1], ah[mt][2], ah[mt][3], sb + AG(0) + (uint32_t)(arow + mt*16)*80 + acol);
                ldm_x4(al[mt][0], al[mt][1], al[mt][2], al[mt][3], sb + AG(1) + (uint32_t)(arow + mt*16)*80 + acol);
            }
#pragma unroll
            for (int np = 0; np < 2; np++){
                uint32_t bh[4], bl[4];
                ldm_x4(bh[0], bh[1], bh[2], bh[3], sb + W1T(ch,0) + (uint32_t)(browA + np*16)*80 + bcol);
                ldm_x4(bl[0], bl[1], bl[2], bl[3], sb + W1T(ch,1) + (uint32_t)(browA + np*16)*80 + bcol);
#pragma unroll
                for (int mt = 0; mt < 2; mt++){
                    mma_bf16(acc[mt][np*2],   ah[mt], &bh[0]);
                    mma_bf16(acc[mt][np*2],   al[mt], &bh[0]);
                    mma_bf16(acc[mt][np*2],   ah[mt], &bl[0]);
                    mma_bf16(acc[mt][np*2+1], ah[mt], &bh[2]);
                    mma_bf16(acc[mt][np*2+1], al[mt], &bh[2]);
                    mma_bf16(acc[mt][np*2+1], ah[mt], &bl[2]);
                }
            }
        }
    }

    const int g  = lane >> 2;
    const int tg = lane & 3;
    __syncthreads();
#pragma unroll
    for (int nt = 0; nt < 4; nt++){
        const int nloc = nt*8 + tg*2;
        const float b0 = __ldg(cbA + wc*32 + nloc), b1 = __ldg(cbA + wc*32 + nloc + 1);
#pragma unroll
        for (int mt = 0; mt < 2; mt++){
            const int r0 = wr*32 + mt*16 + g;
#pragma unroll
            for (int half = 0; half < 2; half++){
                const int rr = r0 + half*8;
                float v0 = fmaxf(acc[mt][nt][half*2]   + b0, 0.f);
                float v1 = fmaxf(acc[mt][nt][half*2+1] + b1, 0.f);
                __nv_bfloat16 h0 = __float2bfloat16(v0), h1 = __float2bfloat16(v1);
                *(uint32_t*)(dsm + H2T(wc,0) + rr*80 + nloc*2) = pk2(h0, h1);
                *(uint32_t*)(dsm + H2T(wc,1) + rr*80 + nloc*2) =
                    pk2(__float2bfloat16(v0 - __bfloat162float(h0)),
                        __float2bfloat16(v1 - __bfloat162float(h1)));
            }
        }
    }
    cp_wait<0>();
    __syncthreads();

    // ---- Phase B: warp tile 32x64, acc2[2][8][4] ----
    float acc2[2][8][4];
#pragma unroll
    for (int mt = 0; mt < 2; mt++)
#pragma unroll
        for (int nn = 0; nn < 8; nn++)
#pragma unroll
            for (int e = 0; e < 4; e++) acc2[mt][nn][e] = 0.f;

    const int browB = wc*64 + (lane & 7) + (((lane >> 4) & 1) << 3);
    for (int ch = 0; ch < 4; ch++){
        if (ch == 2){ cp_wait<1>(); __syncthreads(); }
        if (ch == 3){ cp_wait<0>(); __syncthreads(); }
        const int buf = ch & 1;
#pragma unroll
        for (int ks = 0; ks < 2; ks++){
            const int k0 = ks * 16;
            const uint32_t acol = (uint32_t)k0*2 + acolL;
            const uint32_t bcol = (uint32_t)k0*2 + bcolL;
            uint32_t ah[2][4], al[2][4];
#pragma unroll
            for (int mt = 0; mt < 2; mt++){
                ldm_x4(ah[mt][0], ah[mt][1], ah[mt][2], ah[mt][3], sb + H2T(ch,0) + (uint32_t)(arow + mt*16)*80 + acol);
                ldm_x4(al[mt][0], al[mt][1], al[mt][2], al[mt][3], sb + H2T(ch,1) + (uint32_t)(arow + mt*16)*80 + acol);
            }
#pragma unroll
            for (int np = 0; np < 4; np++){
                uint32_t bh[4], bl[4];
                ldm_x4(bh[0], bh[1], bh[2], bh[3], sb + W2T(buf,0) + (uint32_t)(browB + np*16)*80 + bcol);
                ldm_x4(bl[0], bl[1], bl[2], bl[3], sb + W2T(buf,1) + (uint32_t)(browB + np*16)*80 + bcol);
#pragma unroll
                for (int mt = 0; mt < 2; mt++){
                    mma_bf16(acc2[mt][np*2],   ah[mt], &bh[0]);
                    mma_bf16(acc2[mt][np*2],   al[mt], &bh[0]);
                    mma_bf16(acc2[mt][np*2],   ah[mt], &bl[0]);
                    mma_bf16(acc2[mt][np*2+1], ah[mt], &bh[2]);
                    mma_bf16(acc2[mt][np*2+1], al[mt], &bh[2]);
                    mma_bf16(acc2[mt][np*2+1], ah[mt], &bl[2]);
                }
            }
        }
        if (ch < 2){
            __syncthreads();
            cpW2(ch + 2, buf);
            cp_commit();
        }
    }

#pragma unroll
    for (int mt = 0; mt < 2; mt++){
        const int r0 = m0 + wr*32 + mt*16 + g;
        const int tA = d_idx[r0], tB = d_idx[r0 + 8];
#pragma unroll
        for (int nn = 0; nn < 8; nn++){
            const int n = wc*64 + nn*8 + tg*2;
            const float b0 = __ldg(cbB + n), b1 = __ldg(cbB + n + 1);
            atomicMax(d_xenc + (size_t)tA*256 + n,     encf(acc2[mt][nn][0] + b0));
            atomicMax(d_xenc + (size_t)tA*256 + n + 1, encf(acc2[mt][nn][1] + b1));
            atomicMax(d_xenc + (size_t)tB*256 + n,     encf(acc2[mt][nn][2] + b0));
            atomicMax(d_xenc + (size_t)tB*256 + n + 1, encf(acc2[mt][nn][3] + b1));
        }
    }
}

// ---------------- mma.sync bf16 split GEMM (modes 3,4,5) — 2 CTAs/SM ----------------
#define TB 10240
#define SMEM_REQ (8*TB)

template<int MODE>
__global__ __launch_bounds__(256, 2)
void gemm_mm(const __nv_bfloat16* __restrict__ whi, const __nv_bfloat16* __restrict__ wlo,
             const float* __restrict__ cb, const float* __restrict__ pos)
{
    constexpr int Nt   = (MODE==3)?256:(MODE==4)?512:1024;
    constexpr int KPAD = (MODE==3)?320:(MODE==4)?256:512;
    constexpr int NCH  = KPAD/32;
    constexpr bool AREG = (MODE==3);

    extern __shared__ char dsm[];
    const uint32_t sb = smem_u32(dsm);

    const int tid  = threadIdx.x;
    const int lane = tid & 31;
    const int warp = tid >> 5;
    const int wr = warp >> 2;
    const int wc = warp & 3;
    const int m0 = blockIdx.y * 128;
    const int n0 = blockIdx.x * 128;

    const int lr  = tid >> 1;
    const int lc0 = (tid & 1) * 16;
    const int am  = m0 + lr;

    auto AH = [&](int buf){ return (uint32_t)(buf*TB); };
    auto AL = [&](int buf){ return (uint32_t)(2*TB + buf*TB); };
    auto BH = [&](int buf){ return (uint32_t)(4*TB + buf*TB); };
    auto BL = [&](int buf){ return (uint32_t)(6*TB + buf*TB); };

    float v[16];
    auto fetchA = [&](int ch){
        const int k = ch*32 + lc0;
        if (k + 15 < 256){
            const unsigned* p = d_xenc + (size_t)am * 256 + k;
#pragma unroll
            for (int q = 0; q < 4; q++){
                uint4 u = *(const uint4*)(p + q*4);
                v[q*4+0]=decf(u.x); v[q*4+1]=decf(u.y); v[q*4+2]=decf(u.z); v[q*4+3]=decf(u.w);
            }
        } else {
#pragma unroll
            for (int j = 0; j < 16; j++){
                int kk = k + j;
                v[j] = (kk < 256) ? decf(d_xenc[(size_t)am*256 + kk])
                     : ((kk < 259) ? pos[(size_t)am*3 + (kk-256)] : 0.f);
            }
        }
    };
    auto stsA = [&](int buf){
        __nv_bfloat16 h[16], l[16];
#pragma unroll
        for (int j = 0; j < 16; j++){
            h[j] = __float2bfloat16(v[j]);
            l[j] = __float2bfloat16(v[j] - __bfloat162float(h[j]));
        }
        const uint32_t off = (uint32_t)lr*80 + (uint32_t)lc0*2;
        *(uint4*)(dsm + AH(buf) + off)      = make_uint4(pk2(h[0],h[1]), pk2(h[2],h[3]), pk2(h[4],h[5]), pk2(h[6],h[7]));
        *(uint4*)(dsm + AH(buf) + off + 16) = make_uint4(pk2(h[8],h[9]), pk2(h[10],h[11]), pk2(h[12],h[13]), pk2(h[14],h[15]));
        *(uint4*)(dsm + AL(buf) + off)      = make_uint4(pk2(l[0],l[1]), pk2(l[2],l[3]), pk2(l[4],l[5]), pk2(l[6],l[7]));
        *(uint4*)(dsm + AL(buf) + off + 16) = make_uint4(pk2(l[8],l[9]), pk2(l[10],l[11]), pk2(l[12],l[13]), pk2(l[14],l[15]));
    };
    auto cpA = [&](int ch, int buf){
        const __nv_bfloat16* srch = (MODE==4) ? d_g1hi : d_g2hi;
        const __nv_bfloat16* srcl = (MODE==4) ? d_g1lo : d_g2lo;
#pragma unroll
        for (int i = 0; i < 2; i++){
            int idx = tid + i*256;
            int row = idx >> 2, c = idx & 3;
            size_t goff = (size_t)(m0 + row) * KPAD + ch*32 + c*8;
            cp_async16(dsm + AH(buf) + row*80 + c*16, srch + goff);
            cp_async16(dsm + AL(buf) + row*80 + c*16, srcl + goff);
        }
    };
    auto cpB = [&](int ch, int buf){
#pragma unroll
        for (int i = 0; i < 2; i++){
            int idx = tid + i*256;
            int row = idx >> 2, c = idx & 3;
            const __nv_bfloat16* gh = whi + (size_t)(n0 + row) * KPAD + ch*32 + c*8;
            const __nv_bfloat16* gl = wlo + (size_t)(n0 + row) * KPAD + ch*32 + c*8;
            cp_async16(dsm + BH(buf) + row*80 + c*16, gh);
            cp_async16(dsm + BL(buf) + row*80 + c*16, gl);
        }
    };

    float acc[4][4][4];
#pragma unroll
    for (int mt = 0; mt < 4; mt++)
#pragma unroll
        for (int nt = 0; nt < 4; nt++)
#pragma unroll
            for (int e = 0; e < 4; e++) acc[mt][nt][e] = 0.f;

    if constexpr (AREG){
        fetchA(0);
        cpB(0, 0); cp_commit();
        stsA(0);
        fetchA(1);
    } else {
        cpA(0, 0); cpB(0, 0); cp_commit();
    }
    cp_wait<0>();
    __syncthreads();

    for (int ch = 0; ch < NCH; ch++){
        const int cur = ch & 1, nxt = cur ^ 1;
        if (ch + 1 < NCH){
            if constexpr (AREG){ cpB(ch + 1, nxt); cp_commit(); }
            else               { cpA(ch + 1, nxt); cpB(ch + 1, nxt); cp_commit(); }
        }

        const uint32_t uAH = sb + AH(cur), uAL = sb + AL(cur);
        const uint32_t uBH = sb + BH(cur), uBL = sb + BL(cur);
        const int arow = wr*64 + (lane & 15);
        const int brow = wc*32 + (lane & 7) + (((lane >> 4) & 1) << 3);

#pragma unroll
        for (int ks = 0; ks < 2; ks++){
            const int k0 = ks * 16;
            const uint32_t acol = (uint32_t)(k0 + ((lane >> 4) << 3)) * 2;
            const uint32_t bcol = (uint32_t)(k0 + (((lane >> 3) & 1) << 3)) * 2;
            uint32_t ah[4][4], al[4][4];
#pragma unroll
            for (int mt = 0; mt < 4; mt++){
                ldm_x4(ah[mt][0], ah[mt][1], ah[mt][2], ah[mt][3], uAH + (uint32_t)(arow + mt*16)*80 + acol);
                ldm_x4(al[mt][0], al[mt][1], al[mt][2], al[mt][3], uAL + (uint32_t)(arow + mt*16)*80 + acol);
            }
#pragma unroll
            for (int np = 0; np < 2; np++){
                uint32_t bh[4], bl[4];
                ldm_x4(bh[0], bh[1], bh[2], bh[3], uBH + (uint32_t)(brow + np*16)*80 + bcol);
                ldm_x4(bl[0], bl[1], bl[2], bl[3], uBL + (uint32_t)(brow + np*16)*80 + bcol);
#pragma unroll
                for (int mt = 0; mt < 4; mt++){
                    mma_bf16(acc[mt][np*2],   ah[mt], &bh[0]);
                    mma_bf16(acc[mt][np*2],   al[mt], &bh[0]);
                    mma_bf16(acc[mt][np*2],   ah[mt], &bl[0]);
                    mma_bf16(acc[mt][np*2+1], ah[mt], &bh[2]);
                    mma_bf16(acc[mt][np*2+1], al[mt], &bh[2]);
                    mma_bf16(acc[mt][np*2+1], ah[mt], &bl[2]);
                }
            }
        }

        if (ch + 1 < NCH){
            if constexpr (AREG){
                stsA(nxt);
                if (ch + 2 < NCH) fetchA(ch + 2);
            }
            cp_wait<0>();
        }
        __syncthreads();
    }

    const int g  = lane >> 2;
    const int tg = lane & 3;

    if constexpr (MODE == 3 || MODE == 4){
        uint32_t* hiP = (uint32_t*)((MODE==3) ? d_g1hi : d_g2hi);
        uint32_t* loP = (uint32_t*)((MODE==3) ? d_g1lo : d_g2lo);
#pragma unroll
        for (int nt = 0; nt < 4; nt++){
            const int n = n0 + wc*32 + nt*8 + tg*2;
            const float b0 = __ldg(cb+n), b1 = __ldg(cb+n+1);
#pragma unroll
            for (int mt = 0; mt < 4; mt++){
                const int r0 = m0 + wr*64 + mt*16 + g;
                split_pair(hiP, loP, ((size_t)r0 * Nt + n) >> 1,
                           fmaxf(acc[mt][nt][0] + b0, 0.f), fmaxf(acc[mt][nt][1] + b1, 0.f));
                split_pair(hiP, loP, ((size_t)(r0+8) * Nt + n) >> 1,
                           fmaxf(acc[mt][nt][2] + b0, 0.f), fmaxf(acc[mt][nt][3] + b1, 0.f));
            }
        }
    } else {
        float* sc = (float*)dsm;
#pragma unroll
        for (int nt = 0; nt < 4; nt++){
#pragma unroll
            for (int cp = 0; cp < 2; cp++){
                float mv = fmaxf(acc[0][nt][cp], acc[0][nt][cp+2]);
#pragma unroll
                for (int mt = 1; mt < 4; mt++)
                    mv = fmaxf(mv, fmaxf(acc[mt][nt][cp], acc[mt][nt][cp+2]));
#pragma unroll
                for (int off = 4; off < 32; off <<= 1)
                    mv = fmaxf(mv, __shfl_xor_sync(0xffffffffu, mv, off));
                if (g == 0) sc[wr*128 + wc*32 + nt*8 + tg*2 + cp] = mv;
            }
        }
        __syncthreads();
        if (tid < 128){
            float mv = fmaxf(sc[tid], sc[128 + tid]) + __ldg(cb + n0 + tid);
            int bb = m0 >> 12;
            atomicMax(&d_scene[bb * 1024 + n0 + tid], encf(mv));
        }
    }
}

// ---------------- predictor stage 1 ----------------
__global__ __launch_bounds__(256) void predictor1(
    const int* __restrict__ qidx,
    const float* __restrict__ pw1, const float* __restrict__ pb1)
{
    __shared__ float ef[1280];
    __shared__ float part[256];
    int b = blockIdx.x, c = blockIdx.y, tid = threadIdx.x;
    int q = b * NPTS + qidx[b];
    if (tid < 256) ef[tid] = decf(d_xenc[q * 256 + tid]);
    for (int i = tid; i < 1024; i += 256) ef[256 + i] = decf(d_scene[b * 1024 + i]);
    __syncthreads();
    int o   = c * 64 + (tid & 63);
    int seg = tid >> 6;
    float s = 0.f;
    const float* wp = pw1 + o;
#pragma unroll 4
    for (int k = seg * 320; k < seg * 320 + 320; k++)
        s = fmaf(ef[k], wp[k * 512], s);
    part[tid] = s;
    __syncthreads();
    if (tid < 64){
        float vv = part[tid] + part[tid+64] + part[tid+128] + part[tid+192] + pb1[o];
        d_ph1[b * 512 + o] = fmaxf(vv, 0.f);
    }
}

// ---------------- predictor stage 2 ----------------
__global__ __launch_bounds__(256) void predictor2(
    const float* __restrict__ pw2, const float* __restrict__ pb2,
    const float* __restrict__ pw3, const float* __restrict__ pb3,
    float* __restrict__ out)
{
    __shared__ float h1[512];
    __shared__ float h2[256];
    int b = blockIdx.x, tid = threadIdx.x;
    for (int i = tid; i < 512; i += 256) h1[i] = d_ph1[b * 512 + i];
    __syncthreads();
    {
        float s = pb2[tid];
#pragma unroll 4
        for (int k = 0; k < 512; k++) s = fmaf(h1[k], pw2[k*256 + tid], s);
        h2[tid] = fmaxf(s, 0.f);
    }
    __syncthreads();
    if (tid < 16){
        float s = pb3[tid];
#pragma unroll 4
        for (int k = 0; k < 256; k++) s = fmaf(h2[k], pw3[k*16 + tid], s);
        out[b*16 + tid] = s;
    }
}

// ---------------- launch ----------------
extern "C" void kernel_launch(void* const* d_in, const int* in_sizes, int n_in,
                              void* d_out, int out_size)
{
    const float* pos  = (const float*)d_in[0];
    const int*   qidx = (const int*)  d_in[1];
    const float* cw1 = (const float*)d_in[2];
    const float* cb1 = (const float*)d_in[3];
    const float* cg1 = (const float*)d_in[4];
    const float* cs1 = (const float*)d_in[5];
    const float* cw2 = (const float*)d_in[6];
    const float* cb2 = (const float*)d_in[7];
    const float* cg2 = (const float*)d_in[8];
    const float* cs2 = (const float*)d_in[9];
    const float* cw3 = (const float*)d_in[10];
    const float* cb3 = (const float*)d_in[11];
    const float* sw1 = (const float*)d_in[12];
    const float* sb1 = (const float*)d_in[13];
    const float* sg1 = (const float*)d_in[14];
    const float* ss1 = (const float*)d_in[15];
    const float* sw2 = (const float*)d_in[16];
    const float* sb2 = (const float*)d_in[17];
    const float* sg2 = (const float*)d_in[18];
    const float* ss2 = (const float*)d_in[19];
    const float* sw3 = (const float*)d_in[20];
    const float* sb3 = (const float*)d_in[21];
    const float* pw1 = (const float*)d_in[22];
    const float* pb1 = (const float*)d_in[23];
    const float* pw2 = (const float*)d_in[24];
    const float* pb2 = (const float*)d_in[25];
    const float* pw3 = (const float*)d_in[26];
    const float* pb3 = (const float*)d_in[27];

    cudaFuncSetAttribute(knn_kernel, cudaFuncAttributeMaxDynamicSharedMemorySize, KNN_SMEM);
    cudaFuncSetAttribute(edge_fused, cudaFuncAttributeMaxDynamicSharedMemorySize, EF_SMEM);
    cudaFuncSetAttribute(gemm_mm<3>, cudaFuncAttributeMaxDynamicSharedMemorySize, SMEM_REQ);
    cudaFuncSetAttribute(gemm_mm<4>, cudaFuncAttributeMaxDynamicSharedMemorySize, SMEM_REQ);
    cudaFuncSetAttribute(gemm_mm<5>, cudaFuncAttributeMaxDynamicSharedMemorySize, SMEM_REQ);

    __nv_bfloat16 *w1h, *w1l, *w2h, *w2l, *w3h, *w3l, *w4h, *w4l, *w5h, *w5l;
    cudaGetSymbolAddress((void**)&w1h, d_w1hi); cudaGetSymbolAddress((void**)&w1l, d_w1lo);
    cudaGetSymbolAddress((void**)&w2h, d_w2hi); cudaGetSymbolAddress((void**)&w2l, d_w2lo);
    cudaGetSymbolAddress((void**)&w3h, d_w3hi); cudaGetSymbolAddress((void**)&w3l, d_w3lo);
    cudaGetSymbolAddress((void**)&w4h, d_w4hi); cudaGetSymbolAddress((void**)&w4l, d_w4lo);
    cudaGetSymbolAddress((void**)&w5h, d_w5hi); cudaGetSymbolAddress((void**)&w5l, d_w5lo);
    float* cbp; cudaGetSymbolAddress((void**)&cbp, d_cb);

    // order: init(1), knn(2), prep_all(3), edge_fused(4) <- profiled
    init_kernel<<<(PTOT*256/4 + 255)/256, 256>>>();
    knn_kernel<<<PTOT/8, 256, KNN_SMEM>>>(pos);
    prep_all<<<(PREP_TOTAL + 255)/256, 256>>>(pos, cw1, cb1, cg1, cs1,
                                              cw2, cg2, cb2, cs2, cw3, cb3,
                                              sw1, sg1, sb1, ss1, sw2, sg2, sb2, ss2, sw3, sb3);
    edge_fused<<<EDGES/128, 512, EF_SMEM>>>(w1h, w1l, w2h, w2l, cbp, cbp + 128);

    gemm_mm<3><<<dim3(2, PTOT/128),  256, SMEM_REQ>>>(w3h, w3l, cbp + 384,  pos);
    gemm_mm<4><<<dim3(4, PTOT/128),  256, SMEM_REQ>>>(w4h, w4l, cbp + 640,  nullptr);
    gemm_mm<5><<<dim3(8, PTOT/128),  256, SMEM_REQ>>>(w5h, w5l, cbp + 1152, nullptr);

    predictor1<<<dim3(BATCH, 8), 256>>>(qidx, pw1, pb1);
    predictor2<<<BATCH, 256>>>(pw2, pb2, pw3, pb3, (float*)d_out);
}

// round 15
// speedup vs baseline: 1.0128x; 1.0128x over previous
#include <cuda_runtime.h>
#include <cuda_bf16.h>
#include <cstdint>
#include <cstddef>

#define BATCH 4
#define NPTS  4096
#define PTOT  (BATCH*NPTS)     /* 16384 */
#define KNN   16
#define EDGES (PTOT*KNN)       /* 262144 */
#define FLTMAX 3.402823466e+38f

// ---------------- scratch ----------------
__device__ int      d_idx[EDGES];
__device__ float    d_Ap[PTOT*64];
__device__ float    d_Cp[PTOT*64];
__device__ unsigned d_xenc[PTOT*256];
__device__ __align__(16) __nv_bfloat16 d_g1hi[PTOT*256], d_g1lo[PTOT*256];
__device__ __align__(16) __nv_bfloat16 d_g2hi[PTOT*512], d_g2lo[PTOT*512];
__device__ unsigned d_scene[BATCH*1024];
__device__ float    d_ph1[BATCH*512];
__device__ float    d_cb[2176];

// split weights (gamma-folded): [N, KPAD] bf16, hi/lo
__device__ __align__(16) __nv_bfloat16 d_w1hi[128*64],   d_w1lo[128*64];
__device__ __align__(16) __nv_bfloat16 d_w2hi[256*128],  d_w2lo[256*128];
__device__ __align__(16) __nv_bfloat16 d_w3hi[256*320],  d_w3lo[256*320];
__device__ __align__(16) __nv_bfloat16 d_w4hi[512*256],  d_w4lo[512*256];
__device__ __align__(16) __nv_bfloat16 d_w5hi[1024*512], d_w5lo[1024*512];

__device__ __forceinline__ unsigned encf(float f){
    unsigned u = __float_as_uint(f);
    return (u & 0x80000000u) ? ~u : (u | 0x80000000u);
}
__device__ __forceinline__ float decf(unsigned u){
    return __uint_as_float((u & 0x80000000u) ? (u ^ 0x80000000u) : ~u);
}
__device__ __forceinline__ uint32_t smem_u32(const void* p){
    uint32_t a;
    asm("{ .reg .u64 t; cvta.to.shared.u64 t, %1; cvt.u32.u64 %0, t; }" : "=r"(a) : "l"(p));
    return a;
}
__device__ __forceinline__ void cp_async16(void* smem, const void* gmem){
    unsigned s = (unsigned)__cvta_generic_to_shared(smem);
    asm volatile("cp.async.cg.shared.global [%0], [%1], 16;\n" :: "r"(s), "l"(gmem));
}
__device__ __forceinline__ void cp_commit(){ asm volatile("cp.async.commit_group;\n"); }
template<int N> __device__ __forceinline__ void cp_wait(){
    asm volatile("cp.async.wait_group %0;\n" :: "n"(N));
}

__device__ __forceinline__ void ldm_x4(uint32_t& r0, uint32_t& r1, uint32_t& r2, uint32_t& r3, uint32_t addr){
    asm volatile("ldmatrix.sync.aligned.m8n8.x4.shared.b16 {%0,%1,%2,%3}, [%4];"
        : "=r"(r0), "=r"(r1), "=r"(r2), "=r"(r3) : "r"(addr));
}
__device__ __forceinline__ void mma_bf16(float* c, const uint32_t* a, const uint32_t* b){
    asm volatile(
        "mma.sync.aligned.m16n8k16.row.col.f32.bf16.bf16.f32 "
        "{%0,%1,%2,%3}, {%4,%5,%6,%7}, {%8,%9}, {%0,%1,%2,%3};"
        : "+f"(c[0]), "+f"(c[1]), "+f"(c[2]), "+f"(c[3])
        : "r"(a[0]), "r"(a[1]), "r"(a[2]), "r"(a[3]), "r"(b[0]), "r"(b[1]));
}
__device__ __forceinline__ uint32_t pk2(__nv_bfloat16 a, __nv_bfloat16 b){
    return (uint32_t)__bfloat16_as_ushort(a) | ((uint32_t)__bfloat16_as_ushort(b) << 16);
}
__device__ __forceinline__ void split_pair(uint32_t* hiP, uint32_t* loP, size_t idx2, float v0, float v1){
    __nv_bfloat16 h0 = __float2bfloat16(v0), h1 = __float2bfloat16(v1);
    hiP[idx2] = pk2(h0, h1);
    loP[idx2] = pk2(__float2bfloat16(v0 - __bfloat162float(h0)),
                    __float2bfloat16(v1 - __bfloat162float(h1)));
}

// ---------------- init ----------------
__global__ void init_kernel(){
    int i = blockIdx.x * 256 + threadIdx.x;
    uint4 v = make_uint4(0x00800000u, 0x00800000u, 0x00800000u, 0x00800000u);
    if (i < PTOT*256/4) ((uint4*)d_xenc)[i] = v;
    if (i < BATCH*1024/4) ((uint4*)d_scene)[i] = v;
}

// ---------------- merged prep: Ap/Cp + all weights + fused biases ----------------
#define PREP_AC_N  (PTOT*64)
#define OFF_W      PREP_AC_N
#define PREP_TOTAL (OFF_W + 778240 + 2176)
__global__ void prep_all(
    const float* __restrict__ pos,
    const float* __restrict__ cw1, const float* __restrict__ cb1, const float* __restrict__ cg1, const float* __restrict__ cs1,
    const float* __restrict__ cw2, const float* __restrict__ cg2, const float* __restrict__ cb2, const float* __restrict__ cs2,
    const float* __restrict__ cw3, const float* __restrict__ cb3,
    const float* __restrict__ sw1, const float* __restrict__ sg1, const float* __restrict__ sb1, const float* __restrict__ ss1,
    const float* __restrict__ sw2, const float* __restrict__ sg2, const float* __restrict__ sb2, const float* __restrict__ ss2,
    const float* __restrict__ sw3, const float* __restrict__ sb3)
{
    int raw = blockIdx.x * 256 + threadIdx.x;
    if (raw < PREP_AC_N){
        int p = raw >> 6, j = raw & 63;
        float x = pos[p*3], y = pos[p*3+1], z = pos[p*3+2];
        float w0 = cw1[0*64+j] + cw1[3*64+j];
        float w1 = cw1[1*64+j] + cw1[4*64+j];
        float w2 = cw1[2*64+j] + cw1[5*64+j];
        float a = fmaf(x, w0, fmaf(y, w1, fmaf(z, w2, cb1[j])));
        float c = fmaf(x, cw1[3*64+j], fmaf(y, cw1[4*64+j], z*cw1[5*64+j]));
        float g = cg1[j];
        d_Ap[raw] = fmaf(a, g, cs1[j]);
        d_Cp[raw] = c * g;
        return;
    }
    int idx = raw - OFF_W;
    const float* W; const float* G = nullptr;
    __nv_bfloat16 *hi, *lo;
    int Kt, Nt, KPAD, base;
    if (idx < 8192){        W=cw2; G=cg2; hi=d_w1hi; lo=d_w1lo; Kt=64;  Nt=128;  KPAD=64;  base=0; }
    else if (idx < 40960){  W=cw3;        hi=d_w2hi; lo=d_w2lo; Kt=128; Nt=256;  KPAD=128; base=8192; }
    else if (idx < 122880){ W=sw1; G=sg1; hi=d_w3hi; lo=d_w3lo; Kt=259; Nt=256;  KPAD=320; base=40960; }
    else if (idx < 253952){ W=sw2; G=sg2; hi=d_w4hi; lo=d_w4lo; Kt=256; Nt=512;  KPAD=256; base=122880; }
    else if (idx < 778240){ W=sw3;        hi=d_w5hi; lo=d_w5lo; Kt=512; Nt=1024; KPAD=512; base=253952; }
    else if (idx < 780416){
        int j = idx - 778240;
        if (j < 128)            d_cb[j] = fmaf(cb2[j], cg2[j], cs2[j]);
        else if (j < 384)       d_cb[j] = cb3[j-128];
        else if (j < 640)       d_cb[j] = fmaf(sb1[j-384], sg1[j-384], ss1[j-384]);
        else if (j < 1152)      d_cb[j] = fmaf(sb2[j-640], sg2[j-640], ss2[j-640]);
        else                    d_cb[j] = sb3[j-1152];
        return;
    } else return;
    int li = idx - base;
    int n = li / KPAD, k = li % KPAD;
    float g = G ? G[n] : 1.f;
    float v = (k < Kt) ? W[(size_t)k * Nt + n] * g : 0.f;
    __nv_bfloat16 h = __float2bfloat16(v);
    hi[li] = h;
    lo[li] = __float2bfloat16(v - __bfloat162float(h));
}

// ---------------- kNN: 512 threads, 16 sources per block ----------------
#define KBUF 96
#define KNN_SMEM (3*NPTS*4 + 16*2*KBUF*4)   /* 49152 + 12288 = 61440 */

__global__ __launch_bounds__(512) void knn_kernel(const float* __restrict__ pos){
    extern __shared__ float kb[];
    float* sx = kb; float* sy = kb + NPTS; float* sz = kb + 2*NPTS;
    int b  = blockIdx.x >> 8;              // 256 blocks per batch, 16 sources each
    int s0 = (blockIdx.x & 255) * 16;
    const float* pb = pos + (size_t)b * NPTS * 3;
    for (int i = threadIdx.x; i < NPTS; i += 512){
        sx[i] = pb[3*i]; sy[i] = pb[3*i+1]; sz[i] = pb[3*i+2];
    }
    __syncthreads();

    const int w = threadIdx.x >> 5, lane = threadIdx.x & 31;   // w = 0..15
    float* sD = kb + 3*NPTS + w * 2 * KBUF;
    int*   sI = (int*)(sD + KBUF);
    const int src = s0 + w;
    const float qx = sx[src], qy = sy[src], qz = sz[src];
    const unsigned lmask = (1u << lane) - 1u;

    float td = FLTMAX; int ti = 0x7FFFFFFF;
    int cnt = 0;

    auto compact = [&](){
        float cd[3]; unsigned ca[3];
#pragma unroll
        for (int j = 0; j < 3; j++){
            int e = lane + 32*j;
            bool valid = e < cnt;
            cd[j] = valid ? sD[e] : FLTMAX;
            ca[j] = valid ? ((((unsigned)sI[e]) << 8) | (unsigned)e) : 0xFFFFFFFFu;
        }
        unsigned used = 0;
        float lastd = 0.f; unsigned lasta = 0;
#pragma unroll 1
        for (int r = 0; r < 16; r++){
            float bd = FLTMAX; unsigned ba = 0xFFFFFFFFu;
#pragma unroll
            for (int j = 0; j < 3; j++){
                bool ok = !((used >> j) & 1);
                if (ok && (cd[j] < bd || (cd[j] == bd && ca[j] < ba))){ bd = cd[j]; ba = ca[j]; }
            }
#pragma unroll
            for (int off = 16; off; off >>= 1){
                float od = __shfl_xor_sync(0xffffffffu, bd, off);
                unsigned oa = __shfl_xor_sync(0xffffffffu, ba, off);
                if (od < bd || (od == bd && oa < ba)){ bd = od; ba = oa; }
            }
            unsigned e = ba & 0xFFu;
            if (lane == (int)(e & 31u)) used |= 1u << (e >> 5);
            if (lane == 0){ sD[r] = bd; sI[r] = (int)(ba >> 8); }
            lastd = bd; lasta = ba;
        }
        cnt = 16;
        td = lastd; ti = (int)(lasta >> 8);
        __syncwarp();
    };

    for (int c = lane; c < NPTS; c += 32){
        float dx = qx - sx[c], dy = qy - sy[c], dz = qz - sz[c];
        float d = __fadd_rn(__fadd_rn(__fmul_rn(dx,dx), __fmul_rn(dy,dy)), __fmul_rn(dz,dz));
        bool surv = (d < td) || (d == td && c < ti);
        unsigned m = __ballot_sync(0xffffffffu, surv);
        if (m){
            int pos2 = cnt + __popc(m & lmask);
            if (surv){ sD[pos2] = d; sI[pos2] = c; }
            cnt += __popc(m);
            if (cnt > KBUF - 32) compact();
        }
    }
    compact();

    if (lane < KNN)
        d_idx[(b*NPTS + src) * KNN + lane] = b*NPTS + sI[lane];
}

// ================= fused edge pipeline — 512 threads, 16 warps =================
#define EF_SMEM 225280

__global__ __launch_bounds__(512, 1)
void edge_fused(const __nv_bfloat16* __restrict__ w1h, const __nv_bfloat16* __restrict__ w1l,
                const __nv_bfloat16* __restrict__ w2h, const __nv_bfloat16* __restrict__ w2l,
                const float* __restrict__ cbA, const float* __restrict__ cbB)
{
    extern __shared__ char dsm[];
    const uint32_t sb = smem_u32(dsm);

    const int tid  = threadIdx.x;
    const int lane = tid & 31;
    const int warp = tid >> 5;
    const int wr = warp >> 2;
    const int wc = warp & 3;
    const int m0 = blockIdx.x * 128;

    auto W1T = [&](int ch, int pl){ return (uint32_t)((ch*2 + pl) * 10240); };
    auto AG  = [&](int pl){ return (uint32_t)(40960 + pl*10240); };
    auto H2T = [&](int ch, int pl){ return (uint32_t)(61440 + ch*20480 + pl*10240); };
    auto W2T = [&](int buf, int pl){ return (uint32_t)(143360 + buf*40960 + pl*20480); };

    const int lr  = tid >> 2;
    const int lc0 = (tid & 3) * 8;
    const int am  = m0 + lr;
    const int tgt1 = d_idx[am];

#pragma unroll
    for (int i = 0; i < 4; i++){
        int idx = tid + i*512;
        int unit = idx & 511, grp = idx >> 9;
        int row = unit >> 2, c = unit & 3;
        int ch = grp & 1, pl = grp >> 1;
        const __nv_bfloat16* src = (pl ? w1l : w1h) + (size_t)row*64 + ch*32 + c*8;
        cp_async16(dsm + W1T(ch, pl) + row*80 + c*16, src);
    }
    cp_commit();

    auto cpW2 = [&](int ch, int buf){
#pragma unroll
        for (int i = 0; i < 4; i++){
            int idx = tid + i*512;
            int pl = idx >> 10;
            int unit = idx & 1023;
            int row = unit >> 2, c = unit & 3;
            const __nv_bfloat16* src = (pl ? w2l : w2h) + (size_t)row*128 + ch*32 + c*8;
            cp_async16(dsm + W2T(buf, pl) + row*80 + c*16, src);
        }
    };
    cpW2(0, 0); cp_commit();
    cpW2(1, 1); cp_commit();

    float v[8];
    auto fetchA = [&](int ch){
        const int k = ch*32 + lc0;
        const float* p1 = d_Ap + (size_t)(am >> 4) * 64 + k;
        const float* p2 = d_Cp + (size_t)tgt1 * 64 + k;
        float4 a0 = *(const float4*)p1, a1 = *(const float4*)(p1+4);
        float4 c0 = *(const float4*)p2, c1 = *(const float4*)(p2+4);
        v[0]=fmaxf(a0.x-c0.x,0.f); v[1]=fmaxf(a0.y-c0.y,0.f);
        v[2]=fmaxf(a0.z-c0.z,0.f); v[3]=fmaxf(a0.w-c0.w,0.f);
        v[4]=fmaxf(a1.x-c1.x,0.f); v[5]=fmaxf(a1.y-c1.y,0.f);
        v[6]=fmaxf(a1.z-c1.z,0.f); v[7]=fmaxf(a1.w-c1.w,0.f);
    };
    auto stsA = [&](){
        __nv_bfloat16 h[8], l[8];
#pragma unroll
        for (int j = 0; j < 8; j++){
            h[j] = __float2bfloat16(v[j]);
            l[j] = __float2bfloat16(v[j] - __bfloat162float(h[j]));
        }
        const uint32_t off = (uint32_t)lr*80 + (uint32_t)lc0*2;
        *(uint4*)(dsm + AG(0) + off) = make_uint4(pk2(h[0],h[1]), pk2(h[2],h[3]), pk2(h[4],h[5]), pk2(h[6],h[7]));
        *(uint4*)(dsm + AG(1) + off) = make_uint4(pk2(l[0],l[1]), pk2(l[2],l[3]), pk2(l[4],l[5]), pk2(l[6],l[7]));
    };

    const int arow = wr*32 + (lane & 15);
    const uint32_t acolL = (uint32_t)((lane >> 4) << 3) * 2;
    const uint32_t bcolL = (uint32_t)(((lane >> 3) & 1) << 3) * 2;

    float acc[2][4][4];
#pragma unroll
    for (int mt = 0; mt < 2; mt++)
#pragma unroll
        for (int nt = 0; nt < 4; nt++)
#pragma unroll
            for (int e = 0; e < 4; e++) acc[mt][nt][e] = 0.f;

    fetchA(0);
    stsA();
    fetchA(1);
    cp_wait<2>();
    __syncthreads();

    const int browA = wc*32 + (lane & 7) + (((lane >> 4) & 1) << 3);
#pragma unroll
    for (int ch = 0; ch < 2; ch++){
        if (ch == 1){
            __syncthreads();
            stsA();
            __syncthreads();
        }
#pragma unroll
        for (int ks = 0; ks < 2; ks++){
            const int k0 = ks * 16;
            const uint32_t acol = (uint32_t)k0*2 + acolL;
            const uint32_t bcol = (uint32_t)k0*2 + bcolL;
            uint32_t ah[2][4], al[2][4];
#pragma unroll
            for (int mt = 0; mt < 2; mt++){
                ldm_x4(ah[mt][0], ah[mt][1], ah[mt][2], ah[mt][3], sb + AG(0) + (uint32_t)(arow + mt*16)*80 + acol);
                ldm_x4(al[mt][0], al[mt][1], al[mt][2], al[mt][3], sb + AG(1) + (uint32_t)(arow + mt*16)*80 + acol);
            }
#pragma unroll
            for (int np = 0; np < 2; np++){
                uint32_t bh[4], bl[4];
                ldm_x4(bh[0], bh[1], bh[2], bh[3], sb + W1T(ch,0) + (uint32_t)(browA + np*16)*80 + bcol);
                ldm_x4(bl[0], bl[1], bl[2], bl[3], sb + W1T(ch,1) + (uint32_t)(browA + np*16)*80 + bcol);
#pragma unroll
                for (int mt = 0; mt < 2; mt++){
                    mma_bf16(acc[mt][np*2],   ah[mt], &bh[0]);
                    mma_bf16(acc[mt][np*2],   al[mt], &bh[0]);
                    mma_bf16(acc[mt][np*2],   ah[mt], &bl[0]);
                    mma_bf16(acc[mt][np*2+1], ah[mt], &bh[2]);
                    mma_bf16(acc[mt][np*2+1], al[mt], &bh[2]);
                    mma_bf16(acc[mt][np*2+1], ah[mt], &bl[2]);
                }
            }
        }
    }

    const int g  = lane >> 2;
    const int tg = lane & 3;
    __syncthreads();
#pragma unroll
    for (int nt = 0; nt < 4; nt++){
        const int nloc = nt*8 + tg*2;
        const float b0 = __ldg(cbA + wc*32 + nloc), b1 = __ldg(cbA + wc*32 + nloc + 1);
#pragma unroll
        for (int mt = 0; mt < 2; mt++){
            const int r0 = wr*32 + mt*16 + g;
#pragma unroll
            for (int half = 0; half < 2; half++){
                const int rr = r0 + half*8;
                float v0 = fmaxf(acc[mt][nt][half*2]   + b0, 0.f);
                float v1 = fmaxf(acc[mt][nt][half*2+1] + b1, 0.f);
                __nv_bfloat16 h0 = __float2bfloat16(v0), h1 = __float2bfloat16(v1);
                *(uint32_t*)(dsm + H2T(wc,0) + rr*80 + nloc*2) = pk2(h0, h1);
                *(uint32_t*)(dsm + H2T(wc,1) + rr*80 + nloc*2) =
                    pk2(__float2bfloat16(v0 - __bfloat162float(h0)),
                        __float2bfloat16(v1 - __bfloat162float(h1)));
            }
        }
    }
    cp_wait<0>();
    __syncthreads();

    float acc2[2][8][4];
#pragma unroll
    for (int mt = 0; mt < 2; mt++)
#pragma unroll
        for (int nn = 0; nn < 8; nn++)
#pragma unroll
            for (int e = 0; e < 4; e++) acc2[mt][nn][e] = 0.f;

    const int browB = wc*64 + (lane & 7) + (((lane >> 4) & 1) << 3);
    for (int ch = 0; ch < 4; ch++){
        if (ch == 2){ cp_wait<1>(); __syncthreads(); }
        if (ch == 3){ cp_wait<0>(); __syncthreads(); }
        const int buf = ch & 1;
#pragma unroll
        for (int ks = 0; ks < 2; ks++){
            const int k0 = ks * 16;
            const uint32_t acol = (uint32_t)k0*2 + acolL;
            const uint32_t bcol = (uint32_t)k0*2 + bcolL;
            uint32_t ah[2][4], al[2][4];
#pragma unroll
            for (int mt = 0; mt < 2; mt++){
                ldm_x4(ah[mt][0], ah[mt][1], ah[mt][2], ah[mt][3], sb + H2T(ch,0) + (uint32_t)(arow + mt*16)*80 + acol);
                ldm_x4(al[mt][0], al[mt][1], al[mt][2], al[mt][3], sb + H2T(ch,1) + (uint32_t)(arow + mt*16)*80 + acol);
            }
#pragma unroll
            for (int np = 0; np < 4; np++){
                uint32_t bh[4], bl[4];
                ldm_x4(bh[0], bh[1], bh[2], bh[3], sb + W2T(buf,0) + (uint32_t)(browB + np*16)*80 + bcol);
                ldm_x4(bl[0], bl[1], bl[2], bl[3], sb + W2T(buf,1) + (uint32_t)(browB + np*16)*80 + bcol);
#pragma unroll
                for (int mt = 0; mt < 2; mt++){
                    mma_bf16(acc2[mt][np*2],   ah[mt], &bh[0]);
                    mma_bf16(acc2[mt][np*2],   al[mt], &bh[0]);
                    mma_bf16(acc2[mt][np*2],   ah[mt], &bl[0]);
                    mma_bf16(acc2[mt][np*2+1], ah[mt], &bh[2]);
                    mma_bf16(acc2[mt][np*2+1], al[mt], &bh[2]);
                    mma_bf16(acc2[mt][np*2+1], ah[mt], &bl[2]);
                }
            }
        }
        if (ch < 2){
            __syncthreads();
            cpW2(ch + 2, buf);
            cp_commit();
        }
    }

#pragma unroll
    for (int mt = 0; mt < 2; mt++){
        const int r0 = m0 + wr*32 + mt*16 + g;
        const int tA = d_idx[r0], tB = d_idx[r0 + 8];
#pragma unroll
        for (int nn = 0; nn < 8; nn++){
            const int n = wc*64 + nn*8 + tg*2;
            const float b0 = __ldg(cbB + n), b1 = __ldg(cbB + n + 1);
            atomicMax(d_xenc + (size_t)tA*256 + n,     encf(acc2[mt][nn][0] + b0));
            atomicMax(d_xenc + (size_t)tA*256 + n + 1, encf(acc2[mt][nn][1] + b1));
            atomicMax(d_xenc + (size_t)tB*256 + n,     encf(acc2[mt][nn][2] + b0));
            atomicMax(d_xenc + (size_t)tB*256 + n + 1, encf(acc2[mt][nn][3] + b1));
        }
    }
}

// ---------------- mma.sync bf16 split GEMM (modes 3,4,5) — 2 CTAs/SM ----------------
#define TB 10240
#define SMEM_REQ (8*TB)

template<int MODE>
__global__ __launch_bounds__(256, 2)
void gemm_mm(const __nv_bfloat16* __restrict__ whi, const __nv_bfloat16* __restrict__ wlo,
             const float* __restrict__ cb, const float* __restrict__ pos)
{
    constexpr int Nt   = (MODE==3)?256:(MODE==4)?512:1024;
    constexpr int KPAD = (MODE==3)?320:(MODE==4)?256:512;
    constexpr int NCH  = KPAD/32;
    constexpr bool AREG = (MODE==3);

    extern __shared__ char dsm[];
    const uint32_t sb = smem_u32(dsm);

    const int tid  = threadIdx.x;
    const int lane = tid & 31;
    const int warp = tid >> 5;
    const int wr = warp >> 2;
    const int wc = warp & 3;
    const int m0 = blockIdx.y * 128;
    const int n0 = blockIdx.x * 128;

    const int lr  = tid >> 1;
    const int lc0 = (tid & 1) * 16;
    const int am  = m0 + lr;

    auto AH = [&](int buf){ return (uint32_t)(buf*TB); };
    auto AL = [&](int buf){ return (uint32_t)(2*TB + buf*TB); };
    auto BH = [&](int buf){ return (uint32_t)(4*TB + buf*TB); };
    auto BL = [&](int buf){ return (uint32_t)(6*TB + buf*TB); };

    float v[16];
    auto fetchA = [&](int ch){
        const int k = ch*32 + lc0;
        if (k + 15 < 256){
            const unsigned* p = d_xenc + (size_t)am * 256 + k;
#pragma unroll
            for (int q = 0; q < 4; q++){
                uint4 u = *(const uint4*)(p + q*4);
                v[q*4+0]=decf(u.x); v[q*4+1]=decf(u.y); v[q*4+2]=decf(u.z); v[q*4+3]=decf(u.w);
            }
        } else {
#pragma unroll
            for (int j = 0; j < 16; j++){
                int kk = k + j;
                v[j] = (kk < 256) ? decf(d_xenc[(size_t)am*256 + kk])
                     : ((kk < 259) ? pos[(size_t)am*3 + (kk-256)] : 0.f);
            }
        }
    };
    auto stsA = [&](int buf){
        __nv_bfloat16 h[16], l[16];
#pragma unroll
        for (int j = 0; j < 16; j++){
            h[j] = __float2bfloat16(v[j]);
            l[j] = __float2bfloat16(v[j] - __bfloat162float(h[j]));
        }
        const uint32_t off = (uint32_t)lr*80 + (uint32_t)lc0*2;
        *(uint4*)(dsm + AH(buf) + off)      = make_uint4(pk2(h[0],h[1]), pk2(h[2],h[3]), pk2(h[4],h[5]), pk2(h[6],h[7]));
        *(uint4*)(dsm + AH(buf) + off + 16) = make_uint4(pk2(h[8],h[9]), pk2(h[10],h[11]), pk2(h[12],h[13]), pk2(h[14],h[15]));
        *(uint4*)(dsm + AL(buf) + off)      = make_uint4(pk2(l[0],l[1]), pk2(l[2],l[3]), pk2(l[4],l[5]), pk2(l[6],l[7]));
        *(uint4*)(dsm + AL(buf) + off + 16) = make_uint4(pk2(l[8],l[9]), pk2(l[10],l[11]), pk2(l[12],l[13]), pk2(l[14],l[15]));
    };
    auto cpA = [&](int ch, int buf){
        const __nv_bfloat16* srch = (MODE==4) ? d_g1hi : d_g2hi;
        const __nv_bfloat16* srcl = (MODE==4) ? d_g1lo : d_g2lo;
#pragma unroll
        for (int i = 0; i < 2; i++){
            int idx = tid + i*256;
            int row = idx >> 2, c = idx & 3;
            size_t goff = (size_t)(m0 + row) * KPAD + ch*32 + c*8;
            cp_async16(dsm + AH(buf) + row*80 + c*16, srch + goff);
            cp_async16(dsm + AL(buf) + row*80 + c*16, srcl + goff);
        }
    };
    auto cpB = [&](int ch, int buf){
#pragma unroll
        for (int i = 0; i < 2; i++){
            int idx = tid + i*256;
            int row = idx >> 2, c = idx & 3;
            const __nv_bfloat16* gh = whi + (size_t)(n0 + row) * KPAD + ch*32 + c*8;
            const __nv_bfloat16* gl = wlo + (size_t)(n0 + row) * KPAD + ch*32 + c*8;
            cp_async16(dsm + BH(buf) + row*80 + c*16, gh);
            cp_async16(dsm + BL(buf) + row*80 + c*16, gl);
        }
    };

    float acc[4][4][4];
#pragma unroll
    for (int mt = 0; mt < 4; mt++)
#pragma unroll
        for (int nt = 0; nt < 4; nt++)
#pragma unroll
            for (int e = 0; e < 4; e++) acc[mt][nt][e] = 0.f;

    if constexpr (AREG){
        fetchA(0);
        cpB(0, 0); cp_commit();
        stsA(0);
        fetchA(1);
    } else {
        cpA(0, 0); cpB(0, 0); cp_commit();
    }
    cp_wait<0>();
    __syncthreads();

    for (int ch = 0; ch < NCH; ch++){
        const int cur = ch & 1, nxt = cur ^ 1;
        if (ch + 1 < NCH){
            if constexpr (AREG){ cpB(ch + 1, nxt); cp_commit(); }
            else               { cpA(ch + 1, nxt); cpB(ch + 1, nxt); cp_commit(); }
        }

        const uint32_t uAH = sb + AH(cur), uAL = sb + AL(cur);
        const uint32_t uBH = sb + BH(cur), uBL = sb + BL(cur);
        const int arow = wr*64 + (lane & 15);
        const int brow = wc*32 + (lane & 7) + (((lane >> 4) & 1) << 3);

#pragma unroll
        for (int ks = 0; ks < 2; ks++){
            const int k0 = ks * 16;
            const uint32_t acol = (uint32_t)(k0 + ((lane >> 4) << 3)) * 2;
            const uint32_t bcol = (uint32_t)(k0 + (((lane >> 3) & 1) << 3)) * 2;
            uint32_t ah[4][4], al[4][4];
#pragma unroll
            for (int mt = 0; mt < 4; mt++){
                ldm_x4(ah[mt][0], ah[mt][1], ah[mt][2], ah[mt][3], uAH + (uint32_t)(arow + mt*16)*80 + acol);
                ldm_x4(al[mt][0], al[mt][1], al[mt][2], al[mt][3], uAL + (uint32_t)(arow + mt*16)*80 + acol);
            }
#pragma unroll
            for (int np = 0; np < 2; np++){
                uint32_t bh[4], bl[4];
                ldm_x4(bh[0], bh[1], bh[2], bh[3], uBH + (uint32_t)(brow + np*16)*80 + bcol);
                ldm_x4(bl[0], bl[1], bl[2], bl[3], uBL + (uint32_t)(brow + np*16)*80 + bcol);
#pragma unroll
                for (int mt = 0; mt < 4; mt++){
                    mma_bf16(acc[mt][np*2],   ah[mt], &bh[0]);
                    mma_bf16(acc[mt][np*2],   al[mt], &bh[0]);
                    mma_bf16(acc[mt][np*2],   ah[mt], &bl[0]);
                    mma_bf16(acc[mt][np*2+1], ah[mt], &bh[2]);
                    mma_bf16(acc[mt][np*2+1], al[mt], &bh[2]);
                    mma_bf16(acc[mt][np*2+1], ah[mt], &bl[2]);
                }
            }
        }

        if (ch + 1 < NCH){
            if constexpr (AREG){
                stsA(nxt);
                if (ch + 2 < NCH) fetchA(ch + 2);
            }
            cp_wait<0>();
        }
        __syncthreads();
    }

    const int g  = lane >> 2;
    const int tg = lane & 3;

    if constexpr (MODE == 3 || MODE == 4){
        uint32_t* hiP = (uint32_t*)((MODE==3) ? d_g1hi : d_g2hi);
        uint32_t* loP = (uint32_t*)((MODE==3) ? d_g1lo : d_g2lo);
#pragma unroll
        for (int nt = 0; nt < 4; nt++){
            const int n = n0 + wc*32 + nt*8 + tg*2;
            const float b0 = __ldg(cb+n), b1 = __ldg(cb+n+1);
#pragma unroll
            for (int mt = 0; mt < 4; mt++){
                const int r0 = m0 + wr*64 + mt*16 + g;
                split_pair(hiP, loP, ((size_t)r0 * Nt + n) >> 1,
                           fmaxf(acc[mt][nt][0] + b0, 0.f), fmaxf(acc[mt][nt][1] + b1, 0.f));
                split_pair(hiP, loP, ((size_t)(r0+8) * Nt + n) >> 1,
                           fmaxf(acc[mt][nt][2] + b0, 0.f), fmaxf(acc[mt][nt][3] + b1, 0.f));
            }
        }
    } else {
        float* sc = (float*)dsm;
#pragma unroll
        for (int nt = 0; nt < 4; nt++){
#pragma unroll
            for (int cp = 0; cp < 2; cp++){
                float mv = fmaxf(acc[0][nt][cp], acc[0][nt][cp+2]);
#pragma unroll
                for (int mt = 1; mt < 4; mt++)
                    mv = fmaxf(mv, fmaxf(acc[mt][nt][cp], acc[mt][nt][cp+2]));
#pragma unroll
                for (int off = 4; off < 32; off <<= 1)
                    mv = fmaxf(mv, __shfl_xor_sync(0xffffffffu, mv, off));
                if (g == 0) sc[wr*128 + wc*32 + nt*8 + tg*2 + cp] = mv;
            }
        }
        __syncthreads();
        if (tid < 128){
            float mv = fmaxf(sc[tid], sc[128 + tid]) + __ldg(cb + n0 + tid);
            int bb = m0 >> 12;
            atomicMax(&d_scene[bb * 1024 + n0 + tid], encf(mv));
        }
    }
}

// ---------------- predictor stage 1 ----------------
__global__ __launch_bounds__(256) void predictor1(
    const int* __restrict__ qidx,
    const float* __restrict__ pw1, const float* __restrict__ pb1)
{
    __shared__ float ef[1280];
    __shared__ float part[256];
    int b = blockIdx.x, c = blockIdx.y, tid = threadIdx.x;
    int q = b * NPTS + qidx[b];
    if (tid < 256) ef[tid] = decf(d_xenc[q * 256 + tid]);
    for (int i = tid; i < 1024; i += 256) ef[256 + i] = decf(d_scene[b * 1024 + i]);
    __syncthreads();
    int o   = c * 64 + (tid & 63);
    int seg = tid >> 6;
    float s = 0.f;
    const float* wp = pw1 + o;
#pragma unroll 4
    for (int k = seg * 320; k < seg * 320 + 320; k++)
        s = fmaf(ef[k], wp[k * 512], s);
    part[tid] = s;
    __syncthreads();
    if (tid < 64){
        float vv = part[tid] + part[tid+64] + part[tid+128] + part[tid+192] + pb1[o];
        d_ph1[b * 512 + o] = fmaxf(vv, 0.f);
    }
}

// ---------------- predictor stage 2 ----------------
__global__ __launch_bounds__(256) void predictor2(
    const float* __restrict__ pw2, const float* __restrict__ pb2,
    const float* __restrict__ pw3, const float* __restrict__ pb3,
    float* __restrict__ out)
{
    __shared__ float h1[512];
    __shared__ float h2[256];
    int b = blockIdx.x, tid = threadIdx.x;
    for (int i = tid; i < 512; i += 256) h1[i] = d_ph1[b * 512 + i];
    __syncthreads();
    {
        float s = pb2[tid];
#pragma unroll 4
        for (int k = 0; k < 512; k++) s = fmaf(h1[k], pw2[k*256 + tid], s);
        h2[tid] = fmaxf(s, 0.f);
    }
    __syncthreads();
    if (tid < 16){
        float s = pb3[tid];
#pragma unroll 4
        for (int k = 0; k < 256; k++) s = fmaf(h2[k], pw3[k*16 + tid], s);
        out[b*16 + tid] = s;
    }
}

// ---------------- launch ----------------
extern "C" void kernel_launch(void* const* d_in, const int* in_sizes, int n_in,
                              void* d_out, int out_size)
{
    const float* pos  = (const float*)d_in[0];
    const int*   qidx = (const int*)  d_in[1];
    const float* cw1 = (const float*)d_in[2];
    const float* cb1 = (const float*)d_in[3];
    const float* cg1 = (const float*)d_in[4];
    const float* cs1 = (const float*)d_in[5];
    const float* cw2 = (const float*)d_in[6];
    const float* cb2 = (const float*)d_in[7];
    const float* cg2 = (const float*)d_in[8];
    const float* cs2 = (const float*)d_in[9];
    const float* cw3 = (const float*)d_in[10];
    const float* cb3 = (const float*)d_in[11];
    const float* sw1 = (const float*)d_in[12];
    const float* sb1 = (const float*)d_in[13];
    const float* sg1 = (const float*)d_in[14];
    const float* ss1 = (const float*)d_in[15];
    const float* sw2 = (const float*)d_in[16];
    const float* sb2 = (const float*)d_in[17];
    const float* sg2 = (const float*)d_in[18];
    const float* ss2 = (const float*)d_in[19];
    const float* sw3 = (const float*)d_in[20];
    const float* sb3 = (const float*)d_in[21];
    const float* pw1 = (const float*)d_in[22];
    const float* pb1 = (const float*)d_in[23];
    const float* pw2 = (const float*)d_in[24];
    const float* pb2 = (const float*)d_in[25];
    const float* pw3 = (const float*)d_in[26];
    const float* pb3 = (const float*)d_in[27];

    cudaFuncSetAttribute(knn_kernel, cudaFuncAttributeMaxDynamicSharedMemorySize, KNN_SMEM);
    cudaFuncSetAttribute(edge_fused, cudaFuncAttributeMaxDynamicSharedMemorySize, EF_SMEM);
    cudaFuncSetAttribute(gemm_mm<3>, cudaFuncAttributeMaxDynamicSharedMemorySize, SMEM_REQ);
    cudaFuncSetAttribute(gemm_mm<4>, cudaFuncAttributeMaxDynamicSharedMemorySize, SMEM_REQ);
    cudaFuncSetAttribute(gemm_mm<5>, cudaFuncAttributeMaxDynamicSharedMemorySize, SMEM_REQ);

    __nv_bfloat16 *w1h, *w1l, *w2h, *w2l, *w3h, *w3l, *w4h, *w4l, *w5h, *w5l;
    cudaGetSymbolAddress((void**)&w1h, d_w1hi); cudaGetSymbolAddress((void**)&w1l, d_w1lo);
    cudaGetSymbolAddress((void**)&w2h, d_w2hi); cudaGetSymbolAddress((void**)&w2l, d_w2lo);
    cudaGetSymbolAddress((void**)&w3h, d_w3hi); cudaGetSymbolAddress((void**)&w3l, d_w3lo);
    cudaGetSymbolAddress((void**)&w4h, d_w4hi); cudaGetSymbolAddress((void**)&w4l, d_w4lo);
    cudaGetSymbolAddress((void**)&w5h, d_w5hi); cudaGetSymbolAddress((void**)&w5l, d_w5lo);
    float* cbp; cudaGetSymbolAddress((void**)&cbp, d_cb);

    // order: init(1), knn(2), prep_all(3), edge_fused(4) <- profiled
    init_kernel<<<(PTOT*256/4 + 255)/256, 256>>>();
    knn_kernel<<<PTOT/16, 512, KNN_SMEM>>>(pos);
    prep_all<<<(PREP_TOTAL + 255)/256, 256>>>(pos, cw1, cb1, cg1, cs1,
                                              cw2, cg2, cb2, cs2, cw3, cb3,
                                              sw1, sg1, sb1, ss1, sw2, sg2, sb2, ss2, sw3, sb3);
    edge_fused<<<EDGES/128, 512, EF_SMEM>>>(w1h, w1l, w2h, w2l, cbp, cbp + 128);

    gemm_mm<3><<<dim3(2, PTOT/128),  256, SMEM_REQ>>>(w3h, w3l, cbp + 384,  pos);
    gemm_mm<4><<<dim3(4, PTOT/128),  256, SMEM_REQ>>>(w4h, w4l, cbp + 640,  nullptr);
    gemm_mm<5><<<dim3(8, PTOT/128),  256, SMEM_REQ>>>(w5h, w5l, cbp + 1152, nullptr);

    predictor1<<<dim3(BATCH, 8), 256>>>(qidx, pw1, pb1);
    predictor2<<<BATCH, 256>>>(pw2, pb2, pw3, pb3, (float*)d_out);
}

// round 17
// speedup vs baseline: 1.0195x; 1.0067x over previous
#include <cuda_runtime.h>
#include <cuda_bf16.h>
#include <cstdint>
#include <cstddef>

#define BATCH 4
#define NPTS  4096
#define PTOT  (BATCH*NPTS)     /* 16384 */
#define KNN   16
#define EDGES (PTOT*KNN)       /* 262144 */
#define FLTMAX 3.402823466e+38f

// ---------------- scratch ----------------
__device__ int      d_idx[EDGES];
__device__ float    d_Ap[PTOT*64];
__device__ float    d_Cp[PTOT*64];
__device__ unsigned d_xenc[PTOT*256];
__device__ __align__(16) __nv_bfloat16 d_g1hi[PTOT*256], d_g1lo[PTOT*256];
__device__ __align__(16) __nv_bfloat16 d_g2hi[PTOT*512], d_g2lo[PTOT*512];
__device__ unsigned d_scene[BATCH*1024];
__device__ float    d_ph1[BATCH*512];
__device__ float    d_cb[2176];

// split weights (gamma-folded): [N, KPAD] bf16, hi/lo
__device__ __align__(16) __nv_bfloat16 d_w1hi[128*64],   d_w1lo[128*64];
__device__ __align__(16) __nv_bfloat16 d_w2hi[256*128],  d_w2lo[256*128];
__device__ __align__(16) __nv_bfloat16 d_w3hi[256*320],  d_w3lo[256*320];
__device__ __align__(16) __nv_bfloat16 d_w4hi[512*256],  d_w4lo[512*256];
__device__ __align__(16) __nv_bfloat16 d_w5hi[1024*512], d_w5lo[1024*512];

__device__ __forceinline__ unsigned encf(float f){
    unsigned u = __float_as_uint(f);
    return (u & 0x80000000u) ? ~u : (u | 0x80000000u);
}
__device__ __forceinline__ float decf(unsigned u){
    return __uint_as_float((u & 0x80000000u) ? (u ^ 0x80000000u) : ~u);
}
__device__ __forceinline__ uint32_t smem_u32(const void* p){
    uint32_t a;
    asm("{ .reg .u64 t; cvta.to.shared.u64 t, %1; cvt.u32.u64 %0, t; }" : "=r"(a) : "l"(p));
    return a;
}
__device__ __forceinline__ void cp_async16(void* smem, const void* gmem){
    unsigned s = (unsigned)__cvta_generic_to_shared(smem);
    asm volatile("cp.async.cg.shared.global [%0], [%1], 16;\n" :: "r"(s), "l"(gmem));
}
__device__ __forceinline__ void cp_commit(){ asm volatile("cp.async.commit_group;\n"); }
template<int N> __device__ __forceinline__ void cp_wait(){
    asm volatile("cp.async.wait_group %0;\n" :: "n"(N));
}

__device__ __forceinline__ void ldm_x4(uint32_t& r0, uint32_t& r1, uint32_t& r2, uint32_t& r3, uint32_t addr){
    asm volatile("ldmatrix.sync.aligned.m8n8.x4.shared.b16 {%0,%1,%2,%3}, [%4];"
        : "=r"(r0), "=r"(r1), "=r"(r2), "=r"(r3) : "r"(addr));
}
__device__ __forceinline__ void mma_bf16(float* c, const uint32_t* a, const uint32_t* b){
    asm volatile(
        "mma.sync.aligned.m16n8k16.row.col.f32.bf16.bf16.f32 "
        "{%0,%1,%2,%3}, {%4,%5,%6,%7}, {%8,%9}, {%0,%1,%2,%3};"
        : "+f"(c[0]), "+f"(c[1]), "+f"(c[2]), "+f"(c[3])
        : "r"(a[0]), "r"(a[1]), "r"(a[2]), "r"(a[3]), "r"(b[0]), "r"(b[1]));
}
__device__ __forceinline__ uint32_t pk2(__nv_bfloat16 a, __nv_bfloat16 b){
    return (uint32_t)__bfloat16_as_ushort(a) | ((uint32_t)__bfloat16_as_ushort(b) << 16);
}
__device__ __forceinline__ void split_pair(uint32_t* hiP, uint32_t* loP, size_t idx2, float v0, float v1){
    __nv_bfloat16 h0 = __float2bfloat16(v0), h1 = __float2bfloat16(v1);
    hiP[idx2] = pk2(h0, h1);
    loP[idx2] = pk2(__float2bfloat16(v0 - __bfloat162float(h0)),
                    __float2bfloat16(v1 - __bfloat162float(h1)));
}

// ---------------- merged prep: Ap/Cp + all weights + fused biases ----------------
#define PREP_AC_N  (PTOT*64)
#define OFF_W      PREP_AC_N
#define PREP_TOTAL (OFF_W + 778240 + 2176)
__global__ void prep_all(
    const float* __restrict__ pos,
    const float* __restrict__ cw1, const float* __restrict__ cb1, const float* __restrict__ cg1, const float* __restrict__ cs1,
    const float* __restrict__ cw2, const float* __restrict__ cg2, const float* __restrict__ cb2, const float* __restrict__ cs2,
    const float* __restrict__ cw3, const float* __restrict__ cb3,
    const float* __restrict__ sw1, const float* __restrict__ sg1, const float* __restrict__ sb1, const float* __restrict__ ss1,
    const float* __restrict__ sw2, const float* __restrict__ sg2, const float* __restrict__ sb2, const float* __restrict__ ss2,
    const float* __restrict__ sw3, const float* __restrict__ sb3)
{
    int raw = blockIdx.x * 256 + threadIdx.x;
    if (raw < PREP_AC_N){
        int p = raw >> 6, j = raw & 63;
        float x = pos[p*3], y = pos[p*3+1], z = pos[p*3+2];
        float w0 = cw1[0*64+j] + cw1[3*64+j];
        float w1 = cw1[1*64+j] + cw1[4*64+j];
        float w2 = cw1[2*64+j] + cw1[5*64+j];
        float a = fmaf(x, w0, fmaf(y, w1, fmaf(z, w2, cb1[j])));
        float c = fmaf(x, cw1[3*64+j], fmaf(y, cw1[4*64+j], z*cw1[5*64+j]));
        float g = cg1[j];
        d_Ap[raw] = fmaf(a, g, cs1[j]);
        d_Cp[raw] = c * g;
        return;
    }
    int idx = raw - OFF_W;
    const float* W; const float* G = nullptr;
    __nv_bfloat16 *hi, *lo;
    int Kt, Nt, KPAD, base;
    if (idx < 8192){        W=cw2; G=cg2; hi=d_w1hi; lo=d_w1lo; Kt=64;  Nt=128;  KPAD=64;  base=0; }
    else if (idx < 40960){  W=cw3;        hi=d_w2hi; lo=d_w2lo; Kt=128; Nt=256;  KPAD=128; base=8192; }
    else if (idx < 122880){ W=sw1; G=sg1; hi=d_w3hi; lo=d_w3lo; Kt=259; Nt=256;  KPAD=320; base=40960; }
    else if (idx < 253952){ W=sw2; G=sg2; hi=d_w4hi; lo=d_w4lo; Kt=256; Nt=512;  KPAD=256; base=122880; }
    else if (idx < 778240){ W=sw3;        hi=d_w5hi; lo=d_w5lo; Kt=512; Nt=1024; KPAD=512; base=253952; }
    else if (idx < 780416){
        int j = idx - 778240;
        if (j < 128)            d_cb[j] = fmaf(cb2[j], cg2[j], cs2[j]);
        else if (j < 384)       d_cb[j] = cb3[j-128];
        else if (j < 640)       d_cb[j] = fmaf(sb1[j-384], sg1[j-384], ss1[j-384]);
        else if (j < 1152)      d_cb[j] = fmaf(sb2[j-640], sg2[j-640], ss2[j-640]);
        else                    d_cb[j] = sb3[j-1152];
        return;
    } else return;
    int li = idx - base;
    int n = li / KPAD, k = li % KPAD;
    float g = G ? G[n] : 1.f;
    float v = (k < Kt) ? W[(size_t)k * Nt + n] * g : 0.f;
    __nv_bfloat16 h = __float2bfloat16(v);
    hi[li] = h;
    lo[li] = __float2bfloat16(v - __bfloat162float(h));
}

// ---------------- kNN: 512 threads, 16 sources per block, fused xenc/scene init ----------------
#define KBUF 96
#define KNN_SMEM (3*NPTS*4 + 16*2*KBUF*4)   /* 61440 */

__global__ __launch_bounds__(512) void knn_kernel(const float* __restrict__ pos){
    extern __shared__ float kb[];
    float* sx = kb; float* sy = kb + NPTS; float* sz = kb + 2*NPTS;
    int b  = blockIdx.x >> 8;
    int s0 = (blockIdx.x & 255) * 16;

    // fused init: 1024 blocks x 512 threads cover xenc (1M uint4) + scene (1K uint4)
    {
        const uint4 iv = make_uint4(0x00800000u, 0x00800000u, 0x00800000u, 0x00800000u);
        int g0 = blockIdx.x * 512 + threadIdx.x;
        ((uint4*)d_xenc)[g0] = iv;
        ((uint4*)d_xenc)[g0 + 524288] = iv;
        if (g0 < BATCH*1024/4) ((uint4*)d_scene)[g0] = iv;
    }

    const float* pb = pos + (size_t)b * NPTS * 3;
    for (int i = threadIdx.x; i < NPTS; i += 512){
        sx[i] = pb[3*i]; sy[i] = pb[3*i+1]; sz[i] = pb[3*i+2];
    }
    __syncthreads();

    const int w = threadIdx.x >> 5, lane = threadIdx.x & 31;
    float* sD = kb + 3*NPTS + w * 2 * KBUF;
    int*   sI = (int*)(sD + KBUF);
    const int src = s0 + w;
    const float qx = sx[src], qy = sy[src], qz = sz[src];
    const unsigned lmask = (1u << lane) - 1u;

    float td = FLTMAX; int ti = 0x7FFFFFFF;
    int cnt = 0;

    auto compact = [&](){
        float cd[3]; unsigned ca[3];
#pragma unroll
        for (int j = 0; j < 3; j++){
            int e = lane + 32*j;
            bool valid = e < cnt;
            cd[j] = valid ? sD[e] : FLTMAX;
            ca[j] = valid ? ((((unsigned)sI[e]) << 8) | (unsigned)e) : 0xFFFFFFFFu;
        }
        unsigned used = 0;
        float lastd = 0.f; unsigned lasta = 0;
#pragma unroll 1
        for (int r = 0; r < 16; r++){
            float bd = FLTMAX; unsigned ba = 0xFFFFFFFFu;
#pragma unroll
            for (int j = 0; j < 3; j++){
                bool ok = !((used >> j) & 1);
                if (ok && (cd[j] < bd || (cd[j] == bd && ca[j] < ba))){ bd = cd[j]; ba = ca[j]; }
            }
#pragma unroll
            for (int off = 16; off; off >>= 1){
                float od = __shfl_xor_sync(0xffffffffu, bd, off);
                unsigned oa = __shfl_xor_sync(0xffffffffu, ba, off);
                if (od < bd || (od == bd && oa < ba)){ bd = od; ba = oa; }
            }
            unsigned e = ba & 0xFFu;
            if (lane == (int)(e & 31u)) used |= 1u << (e >> 5);
            if (lane == 0){ sD[r] = bd; sI[r] = (int)(ba >> 8); }
            lastd = bd; lasta = ba;
        }
        cnt = 16;
        td = lastd; ti = (int)(lasta >> 8);
        __syncwarp();
    };

    for (int c = lane; c < NPTS; c += 32){
        float dx = qx - sx[c], dy = qy - sy[c], dz = qz - sz[c];
        float d = __fadd_rn(__fadd_rn(__fmul_rn(dx,dx), __fmul_rn(dy,dy)), __fmul_rn(dz,dz));
        bool surv = (d < td) || (d == td && c < ti);
        unsigned m = __ballot_sync(0xffffffffu, surv);
        if (m){
            int pos2 = cnt + __popc(m & lmask);
            if (surv){ sD[pos2] = d; sI[pos2] = c; }
            cnt += __popc(m);
            if (cnt > KBUF - 32) compact();
        }
    }
    compact();

    if (lane < KNN)
        d_idx[(b*NPTS + src) * KNN + lane] = b*NPTS + sI[lane];
}

// ================= fused edge pipeline — 512 threads, 16 warps =================
#define EF_SMEM 225280

__global__ __launch_bounds__(512, 1)
void edge_fused(const __nv_bfloat16* __restrict__ w1h, const __nv_bfloat16* __restrict__ w1l,
                const __nv_bfloat16* __restrict__ w2h, const __nv_bfloat16* __restrict__ w2l,
                const float* __restrict__ cbA, const float* __restrict__ cbB)
{
    extern __shared__ char dsm[];
    const uint32_t sb = smem_u32(dsm);

    const int tid  = threadIdx.x;
    const int lane = tid & 31;
    const int warp = tid >> 5;
    const int wr = warp >> 2;
    const int wc = warp & 3;
    const int m0 = blockIdx.x * 128;

    auto W1T = [&](int ch, int pl){ return (uint32_t)((ch*2 + pl) * 10240); };
    auto AG  = [&](int pl){ return (uint32_t)(40960 + pl*10240); };
    auto H2T = [&](int ch, int pl){ return (uint32_t)(61440 + ch*20480 + pl*10240); };
    auto W2T = [&](int buf, int pl){ return (uint32_t)(143360 + buf*40960 + pl*20480); };

    const int lr  = tid >> 2;
    const int lc0 = (tid & 3) * 8;
    const int am  = m0 + lr;
    const int tgt1 = d_idx[am];

#pragma unroll
    for (int i = 0; i < 4; i++){
        int idx = tid + i*512;
        int unit = idx & 511, grp = idx >> 9;
        int row = unit >> 2, c = unit & 3;
        int ch = grp & 1, pl = grp >> 1;
        const __nv_bfloat16* src = (pl ? w1l : w1h) + (size_t)row*64 + ch*32 + c*8;
        cp_async16(dsm + W1T(ch, pl) + row*80 + c*16, src);
    }
    cp_commit();

    auto cpW2 = [&](int ch, int buf){
#pragma unroll
        for (int i = 0; i < 4; i++){
            int idx = tid + i*512;
            int pl = idx >> 10;
            int unit = idx & 1023;
            int row = unit >> 2, c = unit & 3;
            const __nv_bfloat16* src = (pl ? w2l : w2h) + (size_t)row*128 + ch*32 + c*8;
            cp_async16(dsm + W2T(buf, pl) + row*80 + c*16, src);
        }
    };
    cpW2(0, 0); cp_commit();
    cpW2(1, 1); cp_commit();

    float v[8];
    auto fetchA = [&](int ch){
        const int k = ch*32 + lc0;
        const float* p1 = d_Ap + (size_t)(am >> 4) * 64 + k;
        const float* p2 = d_Cp + (size_t)tgt1 * 64 + k;
        float4 a0 = *(const float4*)p1, a1 = *(const float4*)(p1+4);
        float4 c0 = *(const float4*)p2, c1 = *(const float4*)(p2+4);
        v[0]=fmaxf(a0.x-c0.x,0.f); v[1]=fmaxf(a0.y-c0.y,0.f);
        v[2]=fmaxf(a0.z-c0.z,0.f); v[3]=fmaxf(a0.w-c0.w,0.f);
        v[4]=fmaxf(a1.x-c1.x,0.f); v[5]=fmaxf(a1.y-c1.y,0.f);
        v[6]=fmaxf(a1.z-c1.z,0.f); v[7]=fmaxf(a1.w-c1.w,0.f);
    };
    auto stsA = [&](){
        __nv_bfloat16 h[8], l[8];
#pragma unroll
        for (int j = 0; j < 8; j++){
            h[j] = __float2bfloat16(v[j]);
            l[j] = __float2bfloat16(v[j] - __bfloat162float(h[j]));
        }
        const uint32_t off = (uint32_t)lr*80 + (uint32_t)lc0*2;
        *(uint4*)(dsm + AG(0) + off) = make_uint4(pk2(h[0],h[1]), pk2(h[2],h[3]), pk2(h[4],h[5]), pk2(h[6],h[7]));
        *(uint4*)(dsm + AG(1) + off) = make_uint4(pk2(l[0],l[1]), pk2(l[2],l[3]), pk2(l[4],l[5]), pk2(l[6],l[7]));
    };

    const int arow = wr*32 + (lane & 15);
    const uint32_t acolL = (uint32_t)((lane >> 4) << 3) * 2;
    const uint32_t bcolL = (uint32_t)(((lane >> 3) & 1) << 3) * 2;

    float acc[2][4][4];
#pragma unroll
    for (int mt = 0; mt < 2; mt++)
#pragma unroll
        for (int nt = 0; nt < 4; nt++)
#pragma unroll
            for (int e = 0; e < 4; e++) acc[mt][nt][e] = 0.f;

    fetchA(0);
    stsA();
    fetchA(1);
    cp_wait<2>();
    __syncthreads();

    const int browA = wc*32 + (lane & 7) + (((lane >> 4) & 1) << 3);
#pragma unroll
    for (int ch = 0; ch < 2; ch++){
        if (ch == 1){
            __syncthreads();
            stsA();
            __syncthreads();
        }
#pragma unroll
        for (int ks = 0; ks < 2; ks++){
            const int k0 = ks * 16;
            const uint32_t acol = (uint32_t)k0*2 + acolL;
            const uint32_t bcol = (uint32_t)k0*2 + bcolL;
            uint32_t ah[2][4], al[2][4];
#pragma unroll
            for (int mt = 0; mt < 2; mt++){
                ldm_x4(ah[mt][0], ah[mt][1], ah[mt][2], ah[mt][3], sb + AG(0) + (uint32_t)(arow + mt*16)*80 + acol);
                ldm_x4(al[mt][0], al[mt][1], al[mt][2], al[mt][3], sb + AG(1) + (uint32_t)(arow + mt*16)*80 + acol);
            }
#pragma unroll
            for (int np = 0; np < 2; np++){
                uint32_t bh[4], bl[4];
                ldm_x4(bh[0], bh[1], bh[2], bh[3], sb + W1T(ch,0) + (uint32_t)(browA + np*16)*80 + bcol);
                ldm_x4(bl[0], bl[1], bl[2], bl[3], sb + W1T(ch,1) + (uint32_t)(browA + np*16)*80 + bcol);
#pragma unroll
                for (int mt = 0; mt < 2; mt++){
                    mma_bf16(acc[mt][np*2],   ah[mt], &bh[0]);
                    mma_bf16(acc[mt][np*2],   al[mt], &bh[0]);
                    mma_bf16(acc[mt][np*2],   ah[mt], &bl[0]);
                    mma_bf16(acc[mt][np*2+1], ah[mt], &bh[2]);
                    mma_bf16(acc[mt][np*2+1], al[mt], &bh[2]);
                    mma_bf16(acc[mt][np*2+1], ah[mt], &bl[2]);
                }
            }
        }
    }

    const int g  = lane >> 2;
    const int tg = lane & 3;
    __syncthreads();
#pragma unroll
    for (int nt = 0; nt < 4; nt++){
        const int nloc = nt*8 + tg*2;
        const float b0 = __ldg(cbA + wc*32 + nloc), b1 = __ldg(cbA + wc*32 + nloc + 1);
#pragma unroll
        for (int mt = 0; mt < 2; mt++){
            const int r0 = wr*32 + mt*16 + g;
#pragma unroll
            for (int half = 0; half < 2; half++){
                const int rr = r0 + half*8;
                float v0 = fmaxf(acc[mt][nt][half*2]   + b0, 0.f);
                float v1 = fmaxf(acc[mt][nt][half*2+1] + b1, 0.f);
                __nv_bfloat16 h0 = __float2bfloat16(v0), h1 = __float2bfloat16(v1);
                *(uint32_t*)(dsm + H2T(wc,0) + rr*80 + nloc*2) = pk2(h0, h1);
                *(uint32_t*)(dsm + H2T(wc,1) + rr*80 + nloc*2) =
                    pk2(__float2bfloat16(v0 - __bfloat162float(h0)),
                        __float2bfloat16(v1 - __bfloat162float(h1)));
            }
        }
    }
    cp_wait<0>();
    __syncthreads();

    float acc2[2][8][4];
#pragma unroll
    for (int mt = 0; mt < 2; mt++)
#pragma unroll
        for (int nn = 0; nn < 8; nn++)
#pragma unroll
            for (int e = 0; e < 4; e++) acc2[mt][nn][e] = 0.f;

    const int browB = wc*64 + (lane & 7) + (((lane >> 4) & 1) << 3);
    for (int ch = 0; ch < 4; ch++){
        if (ch == 2){ cp_wait<1>(); __syncthreads(); }
        if (ch == 3){ cp_wait<0>(); __syncthreads(); }
        const int buf = ch & 1;
#pragma unroll
        for (int ks = 0; ks < 2; ks++){
            const int k0 = ks * 16;
            const uint32_t acol = (uint32_t)k0*2 + acolL;
            const uint32_t bcol = (uint32_t)k0*2 + bcolL;
            uint32_t ah[2][4], al[2][4];
#pragma unroll
            for (int mt = 0; mt < 2; mt++){
                ldm_x4(ah[mt][0], ah[mt][1], ah[mt][2], ah[mt][3], sb + H2T(ch,0) + (uint32_t)(arow + mt*16)*80 + acol);
                ldm_x4(al[mt][0], al[mt][1], al[mt][2], al[mt][3], sb + H2T(ch,1) + (uint32_t)(arow + mt*16)*80 + acol);
            }
#pragma unroll
            for (int np = 0; np < 4; np++){
                uint32_t bh[4], bl[4];
                ldm_x4(bh[0], bh[1], bh[2], bh[3], sb + W2T(buf,0) + (uint32_t)(browB + np*16)*80 + bcol);
                ldm_x4(bl[0], bl[1], bl[2], bl[3], sb + W2T(buf,1) + (uint32_t)(browB + np*16)*80 + bcol);
#pragma unroll
                for (int mt = 0; mt < 2; mt++){
                    mma_bf16(acc2[mt][np*2],   ah[mt], &bh[0]);
                    mma_bf16(acc2[mt][np*2],   al[mt], &bh[0]);
                    mma_bf16(acc2[mt][np*2],   ah[mt], &bl[0]);
                    mma_bf16(acc2[mt][np*2+1], ah[mt], &bh[2]);
                    mma_bf16(acc2[mt][np*2+1], al[mt], &bh[2]);
                    mma_bf16(acc2[mt][np*2+1], ah[mt], &bl[2]);
                }
            }
        }
        if (ch < 2){
            __syncthreads();
            cpW2(ch + 2, buf);
            cp_commit();
        }
    }

#pragma unroll
    for (int mt = 0; mt < 2; mt++){
        const int r0 = m0 + wr*32 + mt*16 + g;
        const int tA = d_idx[r0], tB = d_idx[r0 + 8];
#pragma unroll
        for (int nn = 0; nn < 8; nn++){
            const int n = wc*64 + nn*8 + tg*2;
            const float b0 = __ldg(cbB + n), b1 = __ldg(cbB + n + 1);
            atomicMax(d_xenc + (size_t)tA*256 + n,     encf(acc2[mt][nn][0] + b0));
            atomicMax(d_xenc + (size_t)tA*256 + n + 1, encf(acc2[mt][nn][1] + b1));
            atomicMax(d_xenc + (size_t)tB*256 + n,     encf(acc2[mt][nn][2] + b0));
            atomicMax(d_xenc + (size_t)tB*256 + n + 1, encf(acc2[mt][nn][3] + b1));
        }
    }
}

// ---------------- mma.sync bf16 split GEMM (modes 3,4,5) — 2 CTAs/SM ----------------
#define TB 10240
#define SMEM_REQ (8*TB)

template<int MODE>
__global__ __launch_bounds__(256, 2)
void gemm_mm(const __nv_bfloat16* __restrict__ whi, const __nv_bfloat16* __restrict__ wlo,
             const float* __restrict__ cb, const float* __restrict__ pos)
{
    constexpr int Nt   = (MODE==3)?256:(MODE==4)?512:1024;
    constexpr int KPAD = (MODE==3)?320:(MODE==4)?256:512;
    constexpr int NCH  = KPAD/32;
    constexpr bool AREG = (MODE==3);

    extern __shared__ char dsm[];
    const uint32_t sb = smem_u32(dsm);

    const int tid  = threadIdx.x;
    const int lane = tid & 31;
    const int warp = tid >> 5;
    const int wr = warp >> 2;
    const int wc = warp & 3;
    const int m0 = blockIdx.y * 128;
    const int n0 = blockIdx.x * 128;

    const int lr  = tid >> 1;
    const int lc0 = (tid & 1) * 16;
    const int am  = m0 + lr;

    auto AH = [&](int buf){ return (uint32_t)(buf*TB); };
    auto AL = [&](int buf){ return (uint32_t)(2*TB + buf*TB); };
    auto BH = [&](int buf){ return (uint32_t)(4*TB + buf*TB); };
    auto BL = [&](int buf){ return (uint32_t)(6*TB + buf*TB); };

    float v[16];
    auto fetchA = [&](int ch){
        const int k = ch*32 + lc0;
        if (k + 15 < 256){
            const unsigned* p = d_xenc + (size_t)am * 256 + k;
#pragma unroll
            for (int q = 0; q < 4; q++){
                uint4 u = *(const uint4*)(p + q*4);
                v[q*4+0]=decf(u.x); v[q*4+1]=decf(u.y); v[q*4+2]=decf(u.z); v[q*4+3]=decf(u.w);
            }
        } else {
#pragma unroll
            for (int j = 0; j < 16; j++){
                int kk = k + j;
                v[j] = (kk < 256) ? decf(d_xenc[(size_t)am*256 + kk])
                     : ((kk < 259) ? pos[(size_t)am*3 + (kk-256)] : 0.f);
            }
        }
    };
    auto stsA = [&](int buf){
        __nv_bfloat16 h[16], l[16];
#pragma unroll
        for (int j = 0; j < 16; j++){
            h[j] = __float2bfloat16(v[j]);
            l[j] = __float2bfloat16(v[j] - __bfloat162float(h[j]));
        }
        const uint32_t off = (uint32_t)lr*80 + (uint32_t)lc0*2;
        *(uint4*)(dsm + AH(buf) + off)      = make_uint4(pk2(h[0],h[1]), pk2(h[2],h[3]), pk2(h[4],h[5]), pk2(h[6],h[7]));
        *(uint4*)(dsm + AH(buf) + off + 16) = make_uint4(pk2(h[8],h[9]), pk2(h[10],h[11]), pk2(h[12],h[13]), pk2(h[14],h[15]));
        *(uint4*)(dsm + AL(buf) + off)      = make_uint4(pk2(l[0],l[1]), pk2(l[2],l[3]), pk2(l[4],l[5]), pk2(l[6],l[7]));
        *(uint4*)(dsm + AL(buf) + off + 16) = make_uint4(pk2(l[8],l[9]), pk2(l[10],l[11]), pk2(l[12],l[13]), pk2(l[14],l[15]));
    };
    auto cpA = [&](int ch, int buf){
        const __nv_bfloat16* srch = (MODE==4) ? d_g1hi : d_g2hi;
        const __nv_bfloat16* srcl = (MODE==4) ? d_g1lo : d_g2lo;
#pragma unroll
        for (int i = 0; i < 2; i++){
            int idx = tid + i*256;
            int row = idx >> 2, c = idx & 3;
            size_t goff = (size_t)(m0 + row) * KPAD + ch*32 + c*8;
            cp_async16(dsm + AH(buf) + row*80 + c*16, srch + goff);
            cp_async16(dsm + AL(buf) + row*80 + c*16, srcl + goff);
        }
    };
    auto cpB = [&](int ch, int buf){
#pragma unroll
        for (int i = 0; i < 2; i++){
            int idx = tid + i*256;
            int row = idx >> 2, c = idx & 3;
            const __nv_bfloat16* gh = whi + (size_t)(n0 + row) * KPAD + ch*32 + c*8;
            const __nv_bfloat16* gl = wlo + (size_t)(n0 + row) * KPAD + ch*32 + c*8;
            cp_async16(dsm + BH(buf) + row*80 + c*16, gh);
            cp_async16(dsm + BL(buf) + row*80 + c*16, gl);
        }
    };

    float acc[4][4][4];
#pragma unroll
    for (int mt = 0; mt < 4; mt++)
#pragma unroll
        for (int nt = 0; nt < 4; nt++)
#pragma unroll
            for (int e = 0; e < 4; e++) acc[mt][nt][e] = 0.f;

    if constexpr (AREG){
        fetchA(0);
        cpB(0, 0); cp_commit();
        stsA(0);
        fetchA(1);
    } else {
        cpA(0, 0); cpB(0, 0); cp_commit();
    }
    cp_wait<0>();
    __syncthreads();

    for (int ch = 0; ch < NCH; ch++){
        const int cur = ch & 1, nxt = cur ^ 1;
        if (ch + 1 < NCH){
            if constexpr (AREG){ cpB(ch + 1, nxt); cp_commit(); }
            else               { cpA(ch + 1, nxt); cpB(ch + 1, nxt); cp_commit(); }
        }

        const uint32_t uAH = sb + AH(cur), uAL = sb + AL(cur);
        const uint32_t uBH = sb + BH(cur), uBL = sb + BL(cur);
        const int arow = wr*64 + (lane & 15);
        const int brow = wc*32 + (lane & 7) + (((lane >> 4) & 1) << 3);

#pragma unroll
        for (int ks = 0; ks < 2; ks++){
            const int k0 = ks * 16;
            const uint32_t acol = (uint32_t)(k0 + ((lane >> 4) << 3)) * 2;
            const uint32_t bcol = (uint32_t)(k0 + (((lane >> 3) & 1) << 3)) * 2;
            uint32_t ah[4][4], al[4][4];
#pragma unroll
            for (int mt = 0; mt < 4; mt++){
                ldm_x4(ah[mt][0], ah[mt][1], ah[mt][2], ah[mt][3], uAH + (uint32_t)(arow + mt*16)*80 + acol);
                ldm_x4(al[mt][0], al[mt][1], al[mt][2], al[mt][3], uAL + (uint32_t)(arow + mt*16)*80 + acol);
            }
#pragma unroll
            for (int np = 0; np < 2; np++){
                uint32_t bh[4], bl[4];
                ldm_x4(bh[0], bh[1], bh[2], bh[3], uBH + (uint32_t)(brow + np*16)*80 + bcol);
                ldm_x4(bl[0], bl[1], bl[2], bl[3], uBL + (uint32_t)(brow + np*16)*80 + bcol);
#pragma unroll
                for (int mt = 0; mt < 4; mt++){
                    mma_bf16(acc[mt][np*2],   ah[mt], &bh[0]);
                    mma_bf16(acc[mt][np*2],   al[mt], &bh[0]);
                    mma_bf16(acc[mt][np*2],   ah[mt], &bl[0]);
                    mma_bf16(acc[mt][np*2+1], ah[mt], &bh[2]);
                    mma_bf16(acc[mt][np*2+1], al[mt], &bh[2]);
                    mma_bf16(acc[mt][np*2+1], ah[mt], &bl[2]);
                }
            }
        }

        if (ch + 1 < NCH){
            if constexpr (AREG){
                stsA(nxt);
                if (ch + 2 < NCH) fetchA(ch + 2);
            }
            cp_wait<0>();
        }
        __syncthreads();
    }

    const int g  = lane >> 2;
    const int tg = lane & 3;

    if constexpr (MODE == 3 || MODE == 4){
        uint32_t* hiP = (uint32_t*)((MODE==3) ? d_g1hi : d_g2hi);
        uint32_t* loP = (uint32_t*)((MODE==3) ? d_g1lo : d_g2lo);
#pragma unroll
        for (int nt = 0; nt < 4; nt++){
            const int n = n0 + wc*32 + nt*8 + tg*2;
            const float b0 = __ldg(cb+n), b1 = __ldg(cb+n+1);
#pragma unroll
            for (int mt = 0; mt < 4; mt++){
                const int r0 = m0 + wr*64 + mt*16 + g;
                split_pair(hiP, loP, ((size_t)r0 * Nt + n) >> 1,
                           fmaxf(acc[mt][nt][0] + b0, 0.f), fmaxf(acc[mt][nt][1] + b1, 0.f));
                split_pair(hiP, loP, ((size_t)(r0+8) * Nt + n) >> 1,
                           fmaxf(acc[mt][nt][2] + b0, 0.f), fmaxf(acc[mt][nt][3] + b1, 0.f));
            }
        }
    } else {
        float* sc = (float*)dsm;
#pragma unroll
        for (int nt = 0; nt < 4; nt++){
#pragma unroll
            for (int cp = 0; cp < 2; cp++){
                float mv = fmaxf(acc[0][nt][cp], acc[0][nt][cp+2]);
#pragma unroll
                for (int mt = 1; mt < 4; mt++)
                    mv = fmaxf(mv, fmaxf(acc[mt][nt][cp], acc[mt][nt][cp+2]));
#pragma unroll
                for (int off = 4; off < 32; off <<= 1)
                    mv = fmaxf(mv, __shfl_xor_sync(0xffffffffu, mv, off));
                if (g == 0) sc[wr*128 + wc*32 + nt*8 + tg*2 + cp] = mv;
            }
        }
        __syncthreads();
        if (tid < 128){
            float mv = fmaxf(sc[tid], sc[128 + tid]) + __ldg(cb + n0 + tid);
            int bb = m0 >> 12;
            atomicMax(&d_scene[bb * 1024 + n0 + tid], encf(mv));
        }
    }
}

// ---------------- predictor stage 1 ----------------
__global__ __launch_bounds__(256) void predictor1(
    const int* __restrict__ qidx,
    const float* __restrict__ pw1, const float* __restrict__ pb1)
{
    __shared__ float ef[1280];
    __shared__ float part[256];
    int b = blockIdx.x, c = blockIdx.y, tid = threadIdx.x;
    int q = b * NPTS + qidx[b];
    if (tid < 256) ef[tid] = decf(d_xenc[q * 256 + tid]);
    for (int i = tid; i < 1024; i += 256) ef[256 + i] = decf(d_scene[b * 1024 + i]);
    __syncthreads();
    int o   = c * 64 + (tid & 63);
    int seg = tid >> 6;
    float s = 0.f;
    const float* wp = pw1 + o;
#pragma unroll 4
    for (int k = seg * 320; k < seg * 320 + 320; k++)
        s = fmaf(ef[k], wp[k * 512], s);
    part[tid] = s;
    __syncthreads();
    if (tid < 64){
        float vv = part[tid] + part[tid+64] + part[tid+128] + part[tid+192] + pb1[o];
        d_ph1[b * 512 + o] = fmaxf(vv, 0.f);
    }
}

// ---------------- predictor stage 2 ----------------
__global__ __launch_bounds__(256) void predictor2(
    const float* __restrict__ pw2, const float* __restrict__ pb2,
    const float* __restrict__ pw3, const float* __restrict__ pb3,
    float* __restrict__ out)
{
    __shared__ float h1[512];
    __shared__ float h2[256];
    int b = blockIdx.x, tid = threadIdx.x;
    for (int i = tid; i < 512; i += 256) h1[i] = d_ph1[b * 512 + i];
    __syncthreads();
    {
        float s = pb2[tid];
#pragma unroll 4
        for (int k = 0; k < 512; k++) s = fmaf(h1[k], pw2[k*256 + tid], s);
        h2[tid] = fmaxf(s, 0.f);
    }
    __syncthreads();
    if (tid < 16){
        float s = pb3[tid];
#pragma unroll 4
        for (int k = 0; k < 256; k++) s = fmaf(h2[k], pw3[k*16 + tid], s);
        out[b*16 + tid] = s;
    }
}

// ---------------- launch ----------------
extern "C" void kernel_launch(void* const* d_in, const int* in_sizes, int n_in,
                              void* d_out, int out_size)
{
    const float* pos  = (const float*)d_in[0];
    const int*   qidx = (const int*)  d_in[1];
    const float* cw1 = (const float*)d_in[2];
    const float* cb1 = (const float*)d_in[3];
    const float* cg1 = (const float*)d_in[4];
    const float* cs1 = (const float*)d_in[5];
    const float* cw2 = (const float*)d_in[6];
    const float* cb2 = (const float*)d_in[7];
    const float* cg2 = (const float*)d_in[8];
    const float* cs2 = (const float*)d_in[9];
    const float* cw3 = (const float*)d_in[10];
    const float* cb3 = (const float*)d_in[11];
    const float* sw1 = (const float*)d_in[12];
    const float* sb1 = (const float*)d_in[13];
    const float* sg1 = (const float*)d_in[14];
    const float* ss1 = (const float*)d_in[15];
    const float* sw2 = (const float*)d_in[16];
    const float* sb2 = (const float*)d_in[17];
    const float* sg2 = (const float*)d_in[18];
    const float* ss2 = (const float*)d_in[19];
    const float* sw3 = (const float*)d_in[20];
    const float* sb3 = (const float*)d_in[21];
    const float* pw1 = (const float*)d_in[22];
    const float* pb1 = (const float*)d_in[23];
    const float* pw2 = (const float*)d_in[24];
    const float* pb2 = (const float*)d_in[25];
    const float* pw3 = (const float*)d_in[26];
    const float* pb3 = (const float*)d_in[27];

    cudaFuncSetAttribute(knn_kernel, cudaFuncAttributeMaxDynamicSharedMemorySize, KNN_SMEM);
    cudaFuncSetAttribute(edge_fused, cudaFuncAttributeMaxDynamicSharedMemorySize, EF_SMEM);
    cudaFuncSetAttribute(gemm_mm<3>, cudaFuncAttributeMaxDynamicSharedMemorySize, SMEM_REQ);
    cudaFuncSetAttribute(gemm_mm<4>, cudaFuncAttributeMaxDynamicSharedMemorySize, SMEM_REQ);
    cudaFuncSetAttribute(gemm_mm<5>, cudaFuncAttributeMaxDynamicSharedMemorySize, SMEM_REQ);

    __nv_bfloat16 *w1h, *w1l, *w2h, *w2l, *w3h, *w3l, *w4h, *w4l, *w5h, *w5l;
    cudaGetSymbolAddress((void**)&w1h, d_w1hi); cudaGetSymbolAddress((void**)&w1l, d_w1lo);
    cudaGetSymbolAddress((void**)&w2h, d_w2hi); cudaGetSymbolAddress((void**)&w2l, d_w2lo);
    cudaGetSymbolAddress((void**)&w3h, d_w3hi); cudaGetSymbolAddress((void**)&w3l, d_w3lo);
    cudaGetSymbolAddress((void**)&w4h, d_w4hi); cudaGetSymbolAddress((void**)&w4l, d_w4lo);
    cudaGetSymbolAddress((void**)&w5h, d_w5hi); cudaGetSymbolAddress((void**)&w5l, d_w5lo);
    float* cbp; cudaGetSymbolAddress((void**)&cbp, d_cb);

    // order: knn(1, includes init), prep_all(2), edge_fused(3), gemm3(4)
    knn_kernel<<<PTOT/16, 512, KNN_SMEM>>>(pos);
    prep_all<<<(PREP_TOTAL + 255)/256, 256>>>(pos, cw1, cb1, cg1, cs1,
                                              cw2, cg2, cb2, cs2, cw3, cb3,
                                              sw1, sg1, sb1, ss1, sw2, sg2, sb2, ss2, sw3, sb3);
    edge_fused<<<EDGES/128, 512, EF_SMEM>>>(w1h, w1l, w2h, w2l, cbp, cbp + 128);

    gemm_mm<3><<<dim3(2, PTOT/128),  256, SMEM_REQ>>>(w3h, w3l, cbp + 384,  pos);
    gemm_mm<4><<<dim3(4, PTOT/128),  256, SMEM_REQ>>>(w4h, w4l, cbp + 640,  nullptr);
    gemm_mm<5><<<dim3(8, PTOT/128),  256, SMEM_REQ>>>(w5h, w5l, cbp + 1152, nullptr);

    predictor1<<<dim3(BATCH, 8), 256>>>(qidx, pw1, pb1);
    predictor2<<<BATCH, 256>>>(pw2, pb2, pw3, pb3, (float*)d_out);
}